// round 1
// baseline (speedup 1.0000x reference)
#include <cuda_runtime.h>
#include <math.h>

// ---------------- problem constants ----------------
#define N_NODES 50000
#define N_EDGES 600000
#define N_PRED  200000
#define ETOT    (N_EDGES + N_NODES)   // edges + self loops = 650000
#define W1      512                   // H1*HID
#define W2      256                   // H2*HID
#define H1      4
#define H2      2
#define BN_EPS  1e-5f

// ---------------- scratch (device globals; no allocation allowed) ----------------
__device__ float g_xl1[N_NODES * W1];
__device__ float g_xr1[N_NODES * W1];
__device__ float g_agg1[N_NODES * W1];
__device__ float g_score1[(size_t)ETOT * H1];
__device__ float g_nmax1[N_NODES * H1];
__device__ float g_nsum1[N_NODES * H1];

__device__ float g_xl2[N_NODES * W2];
__device__ float g_xr2[N_NODES * W2];
__device__ float g_agg2[N_NODES * W2];
__device__ float g_score2[(size_t)ETOT * H2];
__device__ float g_nmax2[N_NODES * H2];
__device__ float g_nsum2[N_NODES * H2];

// ---------------- helpers ----------------
__device__ __forceinline__ void atomicMaxF(float* addr, float v) {
    // monotone two-op trick: works for mixed signs, init must be -inf
    if (v >= 0.0f) atomicMax((int*)addr, __float_as_int(v));
    else           atomicMin((unsigned int*)addr, __float_as_uint(v));
}

__device__ __forceinline__ void redAdd4(float* p, float x, float y, float z, float w) {
    asm volatile("red.global.add.v4.f32 [%0], {%1, %2, %3, %4};"
                 :: "l"(p), "f"(x), "f"(y), "f"(z), "f"(w) : "memory");
}

// ---------------- GEMM: C[M,Nn] = A[M,K] @ B[K,Nn] + bias[Nn] ----------------
// BM=64, BN=64, BK=16, 256 threads, 4x4 per thread
#define BM 64
#define BN 64
#define BK 16
__global__ void gemm_bias(const float* __restrict__ A, const float* __restrict__ B,
                          const float* __restrict__ bias, float* __restrict__ C,
                          int M, int K, int Nn) {
    __shared__ float As[BK][BM];
    __shared__ float Bs[BK][BN];
    int tid = threadIdx.x;
    int m0 = blockIdx.y * BM;
    int n0 = blockIdx.x * BN;

    int arow = tid >> 2;            // 0..63
    int akq  = (tid & 3) * 4;       // 0,4,8,12
    int bk   = tid >> 4;            // 0..15
    int bn   = (tid & 15) * 4;      // 0..60

    int tm = (tid >> 4) * 4;        // 0..60
    int tn = (tid & 15) * 4;        // 0..60

    float acc[4][4];
#pragma unroll
    for (int i = 0; i < 4; i++)
#pragma unroll
        for (int j = 0; j < 4; j++) acc[i][j] = 0.0f;

    for (int k0 = 0; k0 < K; k0 += BK) {
        float4 a4;
        if (m0 + arow < M)
            a4 = *(const float4*)(A + (size_t)(m0 + arow) * K + k0 + akq);
        else
            a4 = make_float4(0.f, 0.f, 0.f, 0.f);
        As[akq + 0][arow] = a4.x;
        As[akq + 1][arow] = a4.y;
        As[akq + 2][arow] = a4.z;
        As[akq + 3][arow] = a4.w;

        float4 b4 = *(const float4*)(B + (size_t)(k0 + bk) * Nn + n0 + bn);
        *(float4*)&Bs[bk][bn] = b4;
        __syncthreads();

#pragma unroll
        for (int k = 0; k < BK; k++) {
            float a[4], b[4];
            float4 av = *(const float4*)&As[k][tm];
            float4 bv = *(const float4*)&Bs[k][tn];
            a[0]=av.x; a[1]=av.y; a[2]=av.z; a[3]=av.w;
            b[0]=bv.x; b[1]=bv.y; b[2]=bv.z; b[3]=bv.w;
#pragma unroll
            for (int i = 0; i < 4; i++)
#pragma unroll
                for (int j = 0; j < 4; j++)
                    acc[i][j] = fmaf(a[i], b[j], acc[i][j]);
        }
        __syncthreads();
    }

    float4 bi = *(const float4*)(bias + n0 + tn);
#pragma unroll
    for (int i = 0; i < 4; i++) {
        int row = m0 + tm + i;
        if (row < M) {
            float4 o;
            o.x = acc[i][0] + bi.x;
            o.y = acc[i][1] + bi.y;
            o.z = acc[i][2] + bi.z;
            o.w = acc[i][3] + bi.w;
            *(float4*)(C + (size_t)row * Nn + n0 + tn) = o;
        }
    }
}

// ---------------- per-layer init: zero accumulator, -inf max, 0 sum ----------------
__global__ void init_layer(float* agg, int aggN, float* nmax, float* nsum, int nm) {
    int idx = blockIdx.x * blockDim.x + threadIdx.x;
    if (idx < aggN) agg[idx] = 0.0f;
    if (idx < nm) {
        nmax[idx] = __int_as_float(0xFF800000);  // -inf
        nsum[idx] = 0.0f;
    }
}

// ---------------- edge pass A: scores + segment max (one warp per edge) --------
__global__ void edge_score(const float* __restrict__ xl, const float* __restrict__ xr,
                           const float* __restrict__ att, const int* __restrict__ ei,
                           int H, float* __restrict__ score, float* __restrict__ nmax) {
    int w = (blockIdx.x * blockDim.x + threadIdx.x) >> 5;
    int lane = threadIdx.x & 31;
    if (w >= ETOT) return;
    int src, dst;
    if (w < N_EDGES) { src = ei[w]; dst = ei[N_EDGES + w]; }
    else             { src = dst = w - N_EDGES; }

    int Wd = H * 128;
    const float4* xls = (const float4*)(xl + (size_t)src * Wd);
    const float4* xrd = (const float4*)(xr + (size_t)dst * Wd);
    const float4* at4 = (const float4*)att;

    for (int h = 0; h < H; h++) {
        float4 a = xls[h * 32 + lane];
        float4 b = xrd[h * 32 + lane];
        float4 wv = at4[h * 32 + lane];
        float ex = a.x + b.x; ex = ex > 0.f ? ex : 0.2f * ex;
        float ey = a.y + b.y; ey = ey > 0.f ? ey : 0.2f * ey;
        float ez = a.z + b.z; ez = ez > 0.f ? ez : 0.2f * ez;
        float ew = a.w + b.w; ew = ew > 0.f ? ew : 0.2f * ew;
        float s = ex * wv.x + ey * wv.y + ez * wv.z + ew * wv.w;
#pragma unroll
        for (int o = 16; o > 0; o >>= 1) s += __shfl_xor_sync(0xFFFFFFFFu, s, o);
        if (lane == 0) {
            score[(size_t)w * H + h] = s;
            atomicMaxF(&nmax[dst * H + h], s);
        }
    }
}

// ---------------- edge pass B: exp + segment sum ----------------
__global__ void edge_exp(const int* __restrict__ ei, int H, float* __restrict__ score,
                         const float* __restrict__ nmax, float* __restrict__ nsum) {
    int idx = blockIdx.x * blockDim.x + threadIdx.x;
    int tot = ETOT * H;
    if (idx >= tot) return;
    int e = idx / H, h = idx - e * H;
    int dst = (e < N_EDGES) ? ei[N_EDGES + e] : (e - N_EDGES);
    float ex = expf(score[idx] - nmax[dst * H + h]);
    score[idx] = ex;
    atomicAdd(&nsum[dst * H + h], ex);
}

// ---------------- edge pass C: alpha * xl[src] scattered to dst ----------------
__global__ void edge_aggr(const float* __restrict__ xl, const int* __restrict__ ei, int H,
                          const float* __restrict__ score, const float* __restrict__ nsum,
                          float* __restrict__ out) {
    int w = (blockIdx.x * blockDim.x + threadIdx.x) >> 5;
    int lane = threadIdx.x & 31;
    if (w >= ETOT) return;
    int src, dst;
    if (w < N_EDGES) { src = ei[w]; dst = ei[N_EDGES + w]; }
    else             { src = dst = w - N_EDGES; }

    int Wd = H * 128;
    const float4* xls = (const float4*)(xl + (size_t)src * Wd);
    float* ob = out + (size_t)dst * Wd;

    for (int h = 0; h < H; h++) {
        float alpha = score[(size_t)w * H + h] / nsum[dst * H + h];
        float4 v = xls[h * 32 + lane];
        redAdd4(ob + h * 128 + lane * 4, alpha * v.x, alpha * v.y, alpha * v.z, alpha * v.w);
    }
}

// ---------------- bias + BN(eval) + ReLU, in place ----------------
__global__ void bn_relu(float* __restrict__ h, const float* __restrict__ bias,
                        const float* __restrict__ g, const float* __restrict__ b,
                        const float* __restrict__ m, const float* __restrict__ v,
                        int total, int Wd) {
    int idx = blockIdx.x * blockDim.x + threadIdx.x;
    if (idx >= total) return;
    int c = idx % Wd;
    float val = h[idx] + bias[c];
    val = (val - m[c]) * rsqrtf(v[c] + BN_EPS) * g[c] + b[c];
    h[idx] = val > 0.f ? val : 0.f;
}

// ---------------- prediction head: one warp per pred edge ----------------
__global__ void head_kernel(const float* __restrict__ z, const int* __restrict__ pe,
                            const float* __restrict__ pr, const float* __restrict__ pert,
                            const float* __restrict__ Wp, const float* __restrict__ bp,
                            float* __restrict__ out) {
    __shared__ float sw[(W2 * 2 + 3) * 2];  // 1030 floats
    for (int i = threadIdx.x; i < (W2 * 2 + 3) * 2; i += blockDim.x) sw[i] = Wp[i];
    __syncthreads();

    int w = (blockIdx.x * blockDim.x + threadIdx.x) >> 5;
    int lane = threadIdx.x & 31;
    if (w >= N_PRED) return;
    int s = pe[w], d = pe[N_PRED + w];
    const float4* zs = (const float4*)(z + (size_t)s * W2);
    const float4* zd = (const float4*)(z + (size_t)d * W2);

    float a0 = 0.f, a1 = 0.f;
#pragma unroll
    for (int q = 0; q < 2; q++) {
        int r = lane * 2 + q;           // float4 index into 256-wide row
        float4 vz = zs[r];
        int base = (r * 4) * 2;
        a0 += vz.x * sw[base] + vz.y * sw[base + 2] + vz.z * sw[base + 4] + vz.w * sw[base + 6];
        a1 += vz.x * sw[base + 1] + vz.y * sw[base + 3] + vz.z * sw[base + 5] + vz.w * sw[base + 7];
        float4 vd = zd[r];
        int base2 = (W2 + r * 4) * 2;
        a0 += vd.x * sw[base2] + vd.y * sw[base2 + 2] + vd.z * sw[base2 + 4] + vd.w * sw[base2 + 6];
        a1 += vd.x * sw[base2 + 1] + vd.y * sw[base2 + 3] + vd.z * sw[base2 + 5] + vd.w * sw[base2 + 7];
    }
    if (lane == 0) {
        float prs = pr[s], prd = pr[d], pp = pert[s] * pert[d];
        int b0 = (2 * W2) * 2;
        a0 += prs * sw[b0] + prd * sw[b0 + 2] + pp * sw[b0 + 4];
        a1 += prs * sw[b0 + 1] + prd * sw[b0 + 3] + pp * sw[b0 + 5];
    }
#pragma unroll
    for (int o = 16; o > 0; o >>= 1) {
        a0 += __shfl_xor_sync(0xFFFFFFFFu, a0, o);
        a1 += __shfl_xor_sync(0xFFFFFFFFu, a1, o);
    }
    if (lane == 0) {
        out[(size_t)w * 2 + 0] = a0 + bp[0];
        out[(size_t)w * 2 + 1] = a1 + bp[1];
    }
}

// ---------------- launch ----------------
extern "C" void kernel_launch(void* const* d_in, const int* in_sizes, int n_in,
                              void* d_out, int out_size) {
    const float* x     = (const float*)d_in[0];
    const int*   ei    = (const int*)d_in[1];
    const int*   pe    = (const int*)d_in[2];
    const float* pert  = (const float*)d_in[3];
    const float* pr    = (const float*)d_in[4];
    const float* Wl1   = (const float*)d_in[5];
    const float* bl1   = (const float*)d_in[6];
    const float* Wr1   = (const float*)d_in[7];
    const float* br1   = (const float*)d_in[8];
    const float* att1  = (const float*)d_in[9];
    const float* bias1 = (const float*)d_in[10];
    const float* bn1g  = (const float*)d_in[11];
    const float* bn1b  = (const float*)d_in[12];
    const float* bn1m  = (const float*)d_in[13];
    const float* bn1v  = (const float*)d_in[14];
    const float* Wl2   = (const float*)d_in[15];
    const float* bl2   = (const float*)d_in[16];
    const float* Wr2   = (const float*)d_in[17];
    const float* br2   = (const float*)d_in[18];
    const float* att2  = (const float*)d_in[19];
    const float* bias2 = (const float*)d_in[20];
    const float* bn2g  = (const float*)d_in[21];
    const float* bn2b  = (const float*)d_in[22];
    const float* bn2m  = (const float*)d_in[23];
    const float* bn2v  = (const float*)d_in[24];
    const float* Wp    = (const float*)d_in[25];
    const float* bp    = (const float*)d_in[26];
    float* out = (float*)d_out;

    float *xl1, *xr1, *agg1, *sc1, *nm1, *ns1;
    float *xl2, *xr2, *agg2, *sc2, *nm2, *ns2;
    cudaGetSymbolAddress((void**)&xl1, g_xl1);
    cudaGetSymbolAddress((void**)&xr1, g_xr1);
    cudaGetSymbolAddress((void**)&agg1, g_agg1);
    cudaGetSymbolAddress((void**)&sc1, g_score1);
    cudaGetSymbolAddress((void**)&nm1, g_nmax1);
    cudaGetSymbolAddress((void**)&ns1, g_nsum1);
    cudaGetSymbolAddress((void**)&xl2, g_xl2);
    cudaGetSymbolAddress((void**)&xr2, g_xr2);
    cudaGetSymbolAddress((void**)&agg2, g_agg2);
    cudaGetSymbolAddress((void**)&sc2, g_score2);
    cudaGetSymbolAddress((void**)&nm2, g_nmax2);
    cudaGetSymbolAddress((void**)&ns2, g_nsum2);

    const int TB = 256;
    int mblk = (N_NODES + BM - 1) / BM;          // 782
    int eblk = (ETOT * 32 + TB - 1) / TB;        // warp per edge

    // ---- layer 1 ----
    {
        dim3 g1(W1 / BN, mblk);
        gemm_bias<<<g1, TB>>>(x, Wl1, bl1, xl1, N_NODES, 128, W1);
        gemm_bias<<<g1, TB>>>(x, Wr1, br1, xr1, N_NODES, 128, W1);
    }
    {
        int aggN = N_NODES * W1, nm = N_NODES * H1;
        init_layer<<<(aggN + TB - 1) / TB, TB>>>(agg1, aggN, nm1, ns1, nm);
    }
    edge_score<<<eblk, TB>>>(xl1, xr1, att1, ei, H1, sc1, nm1);
    {
        int tot = ETOT * H1;
        edge_exp<<<(tot + TB - 1) / TB, TB>>>(ei, H1, sc1, nm1, ns1);
    }
    edge_aggr<<<eblk, TB>>>(xl1, ei, H1, sc1, ns1, agg1);
    {
        int tot = N_NODES * W1;
        bn_relu<<<(tot + TB - 1) / TB, TB>>>(agg1, bias1, bn1g, bn1b, bn1m, bn1v, tot, W1);
    }

    // ---- layer 2 ----
    {
        dim3 g2(W2 / BN, mblk);
        gemm_bias<<<g2, TB>>>(agg1, Wl2, bl2, xl2, N_NODES, W1, W2);
        gemm_bias<<<g2, TB>>>(agg1, Wr2, br2, xr2, N_NODES, W1, W2);
    }
    {
        int aggN = N_NODES * W2, nm = N_NODES * H2;
        init_layer<<<(aggN + TB - 1) / TB, TB>>>(agg2, aggN, nm2, ns2, nm);
    }
    edge_score<<<eblk, TB>>>(xl2, xr2, att2, ei, H2, sc2, nm2);
    {
        int tot = ETOT * H2;
        edge_exp<<<(tot + TB - 1) / TB, TB>>>(ei, H2, sc2, nm2, ns2);
    }
    edge_aggr<<<eblk, TB>>>(xl2, ei, H2, sc2, ns2, agg2);
    {
        int tot = N_NODES * W2;
        bn_relu<<<(tot + TB - 1) / TB, TB>>>(agg2, bias2, bn2g, bn2b, bn2m, bn2v, tot, W2);
    }

    // ---- head ----
    head_kernel<<<(N_PRED * 32 + TB - 1) / TB, TB>>>(agg2, pe, pr, pert, Wp, bp, out);
}

// round 2
// speedup vs baseline: 1.2572x; 1.2572x over previous
#include <cuda_runtime.h>
#include <math.h>

// ---------------- problem constants ----------------
#define N_NODES 50000
#define N_EDGES 600000
#define N_PRED  200000
#define ETOT    (N_EDGES + N_NODES)   // edges + self loops = 650000
#define W1      512                   // H1*HID
#define W2      256                   // H2*HID
#define H1      4
#define H2      2
#define BN_EPS  1e-5f

// ---------------- scratch (device globals; no allocation allowed) ----------------
__device__ float g_xl1[N_NODES * W1];
__device__ float g_xr1[N_NODES * W1];
__device__ float g_agg1[N_NODES * W1];
__device__ float g_score1[(size_t)ETOT * H1];
__device__ float g_nmax1[N_NODES * H1];
__device__ float g_nsum1[N_NODES * H1];

__device__ float g_xl2[N_NODES * W2];
__device__ float g_xr2[N_NODES * W2];
__device__ float g_agg2[N_NODES * W2];
__device__ float g_score2[(size_t)ETOT * H2];
__device__ float g_nmax2[N_NODES * H2];
__device__ float g_nsum2[N_NODES * H2];

__device__ float g_bns1[W1];   // fused bias1+BN1 scale
__device__ float g_bnt1[W1];   // fused bias1+BN1 shift

// ---------------- helpers ----------------
__device__ __forceinline__ void atomicMaxF(float* addr, float v) {
    if (v >= 0.0f) atomicMax((int*)addr, __float_as_int(v));
    else           atomicMin((unsigned int*)addr, __float_as_uint(v));
}

__device__ __forceinline__ void redAdd4(float* p, float x, float y, float z, float w) {
    asm volatile("red.global.add.v4.f32 [%0], {%1, %2, %3, %4};"
                 :: "l"(p), "f"(x), "f"(y), "f"(z), "f"(w) : "memory");
}

__device__ __forceinline__ unsigned long long pk2(float x, float y) {
    unsigned long long r;
    asm("mov.b64 %0, {%1, %2};" : "=l"(r) : "f"(x), "f"(y));
    return r;
}
__device__ __forceinline__ void fma2(unsigned long long& c, unsigned long long a,
                                     unsigned long long b) {
    asm("fma.rn.f32x2 %0, %1, %2, %0;" : "+l"(c) : "l"(a), "l"(b));
}
__device__ __forceinline__ float2 upk2(unsigned long long u) {
    float2 f;
    asm("mov.b64 {%0, %1}, %2;" : "=f"(f.x), "=f"(f.y) : "l"(u));
    return f;
}

// ---------------- FFMA2 GEMM: C[M,Nn] = op(A)[M,K] @ B[K,Nn] + bias ----------------
// 128x128 tile, BK=16, 256 threads, 8x8 per thread via f32x2.
// FUSE_BN: A elements transformed a' = relu(a*bns[k] + bnt[k]) on load.
#define GBM 128
#define GBN 128
#define GBK 16

template<bool FUSE_BN>
__global__ __launch_bounds__(256, 2)
void gemm_f2(const float* __restrict__ A, const float* __restrict__ B,
             const float* __restrict__ bias, float* __restrict__ C,
             int M, int K, int Nn,
             const float* __restrict__ bns, const float* __restrict__ bnt) {
    __shared__ float As[2][GBK][GBM];
    __shared__ float Bs[2][GBK][GBN];
    int tid = threadIdx.x;
    int m0 = blockIdx.y * GBM;
    int n0 = blockIdx.x * GBN;

    // global->smem load mapping
    int lrow = tid >> 1;              // 0..127 (A row within tile)
    int lkq  = (tid & 1) * 8;         // 0 or 8 (A k offset)
    int bkr  = tid >> 4;              // 0..15  (B k row)
    int bnq  = (tid & 15) * 8;        // 0..120 (B n offset)

    // compute mapping
    int tx = tid & 15;
    int ty = tid >> 4;
    int tx4 = tx * 4;
    int ty4 = ty * 4;

    unsigned long long acc[4][8];
#pragma unroll
    for (int p = 0; p < 4; p++)
#pragma unroll
        for (int j = 0; j < 8; j++) acc[p][j] = 0ull;

    float ar[8], br[8];
    int niter = K / GBK;

    auto loadA = [&](int k0) {
        int row = m0 + lrow;
        if (row < M) {
            float4 v0 = *(const float4*)(A + (size_t)row * K + k0 + lkq);
            float4 v1 = *(const float4*)(A + (size_t)row * K + k0 + lkq + 4);
            ar[0] = v0.x; ar[1] = v0.y; ar[2] = v0.z; ar[3] = v0.w;
            ar[4] = v1.x; ar[5] = v1.y; ar[6] = v1.z; ar[7] = v1.w;
        } else {
#pragma unroll
            for (int i = 0; i < 8; i++) ar[i] = 0.0f;
        }
        if (FUSE_BN) {
#pragma unroll
            for (int i = 0; i < 8; i++) {
                int c = k0 + lkq + i;
                ar[i] = fmaxf(fmaf(ar[i], bns[c], bnt[c]), 0.0f);
            }
        }
    };
    auto loadB = [&](int k0) {
        const float4* p = (const float4*)(B + (size_t)(k0 + bkr) * Nn + n0 + bnq);
        float4 v0 = p[0], v1 = p[1];
        br[0] = v0.x; br[1] = v0.y; br[2] = v0.z; br[3] = v0.w;
        br[4] = v1.x; br[5] = v1.y; br[6] = v1.z; br[7] = v1.w;
    };
    auto stA = [&](int b) {
#pragma unroll
        for (int i = 0; i < 8; i++) As[b][lkq + i][lrow] = ar[i];
    };
    auto stB = [&](int b) {
        *(float4*)&Bs[b][bkr][bnq]     = make_float4(br[0], br[1], br[2], br[3]);
        *(float4*)&Bs[b][bkr][bnq + 4] = make_float4(br[4], br[5], br[6], br[7]);
    };

    loadA(0); loadB(0);
    stA(0);   stB(0);
    __syncthreads();

    for (int it = 0; it < niter; it++) {
        int cb = it & 1;
        if (it + 1 < niter) { loadA((it + 1) * GBK); loadB((it + 1) * GBK); }
#pragma unroll
        for (int k = 0; k < GBK; k++) {
            float4 a0 = *(const float4*)&As[cb][k][ty4];
            float4 a1 = *(const float4*)&As[cb][k][64 + ty4];
            float4 b0 = *(const float4*)&Bs[cb][k][tx4];
            float4 b1 = *(const float4*)&Bs[cb][k][64 + tx4];
            unsigned long long aa[4], bb[8];
            aa[0] = pk2(a0.x, a0.y); aa[1] = pk2(a0.z, a0.w);
            aa[2] = pk2(a1.x, a1.y); aa[3] = pk2(a1.z, a1.w);
            bb[0] = pk2(b0.x, b0.x); bb[1] = pk2(b0.y, b0.y);
            bb[2] = pk2(b0.z, b0.z); bb[3] = pk2(b0.w, b0.w);
            bb[4] = pk2(b1.x, b1.x); bb[5] = pk2(b1.y, b1.y);
            bb[6] = pk2(b1.z, b1.z); bb[7] = pk2(b1.w, b1.w);
#pragma unroll
            for (int p = 0; p < 4; p++)
#pragma unroll
                for (int j = 0; j < 8; j++)
                    fma2(acc[p][j], aa[p], bb[j]);
        }
        if (it + 1 < niter) { stA(cb ^ 1); stB(cb ^ 1); __syncthreads(); }
    }

    float4 bi0 = *(const float4*)(bias + n0 + tx4);
    float4 bi1 = *(const float4*)(bias + n0 + 64 + tx4);
#pragma unroll
    for (int p = 0; p < 4; p++) {
        int rbase = (p < 2) ? (m0 + ty4 + 2 * p) : (m0 + 64 + ty4 + 2 * (p - 2));
        float2 v[8];
#pragma unroll
        for (int j = 0; j < 8; j++) v[j] = upk2(acc[p][j]);
        if (rbase < M) {
            float4 o0 = make_float4(v[0].x + bi0.x, v[1].x + bi0.y, v[2].x + bi0.z, v[3].x + bi0.w);
            float4 o1 = make_float4(v[4].x + bi1.x, v[5].x + bi1.y, v[6].x + bi1.z, v[7].x + bi1.w);
            *(float4*)(C + (size_t)rbase * Nn + n0 + tx4)      = o0;
            *(float4*)(C + (size_t)rbase * Nn + n0 + 64 + tx4) = o1;
        }
        if (rbase + 1 < M) {
            float4 o0 = make_float4(v[0].y + bi0.x, v[1].y + bi0.y, v[2].y + bi0.z, v[3].y + bi0.w);
            float4 o1 = make_float4(v[4].y + bi1.x, v[5].y + bi1.y, v[6].y + bi1.z, v[7].y + bi1.w);
            *(float4*)(C + (size_t)(rbase + 1) * Nn + n0 + tx4)      = o0;
            *(float4*)(C + (size_t)(rbase + 1) * Nn + n0 + 64 + tx4) = o1;
        }
    }
}

// ---------------- BN prep: fold bias + eval BN into scale/shift ----------------
__global__ void bn_prep(const float* __restrict__ bias, const float* __restrict__ g,
                        const float* __restrict__ b, const float* __restrict__ m,
                        const float* __restrict__ v, float* __restrict__ s,
                        float* __restrict__ t, int n) {
    int i = blockIdx.x * blockDim.x + threadIdx.x;
    if (i < n) {
        float sc = g[i] * rsqrtf(v[i] + BN_EPS);
        s[i] = sc;
        t[i] = b[i] + (bias[i] - m[i]) * sc;
    }
}

// ---------------- per-layer init ----------------
__global__ void init_layer(float* agg, int aggN, float* nmax, float* nsum, int nm) {
    int idx = blockIdx.x * blockDim.x + threadIdx.x;
    if (idx < aggN) agg[idx] = 0.0f;
    if (idx < nm) {
        nmax[idx] = __int_as_float(0xFF800000);  // -inf
        nsum[idx] = 0.0f;
    }
}

// ---------------- edge pass A: scores + segment max (one warp per edge) --------
template<int H>
__global__ void edge_score(const float* __restrict__ xl, const float* __restrict__ xr,
                           const float* __restrict__ att, const int* __restrict__ ei,
                           float* __restrict__ score, float* __restrict__ nmax) {
    int w = (blockIdx.x * blockDim.x + threadIdx.x) >> 5;
    int lane = threadIdx.x & 31;
    if (w >= ETOT) return;
    int src, dst;
    if (w < N_EDGES) { src = ei[w]; dst = ei[N_EDGES + w]; }
    else             { src = dst = w - N_EDGES; }

    const int Wd = H * 128;
    const float4* xls = (const float4*)(xl + (size_t)src * Wd);
    const float4* xrd = (const float4*)(xr + (size_t)dst * Wd);
    const float4* at4 = (const float4*)att;

#pragma unroll
    for (int h = 0; h < H; h++) {
        float4 a = xls[h * 32 + lane];
        float4 b = xrd[h * 32 + lane];
        float4 wv = at4[h * 32 + lane];
        float ex = a.x + b.x; ex = ex > 0.f ? ex : 0.2f * ex;
        float ey = a.y + b.y; ey = ey > 0.f ? ey : 0.2f * ey;
        float ez = a.z + b.z; ez = ez > 0.f ? ez : 0.2f * ez;
        float ew = a.w + b.w; ew = ew > 0.f ? ew : 0.2f * ew;
        float s = ex * wv.x + ey * wv.y + ez * wv.z + ew * wv.w;
#pragma unroll
        for (int o = 16; o > 0; o >>= 1) s += __shfl_xor_sync(0xFFFFFFFFu, s, o);
        if (lane == 0) {
            score[(size_t)w * H + h] = s;
            atomicMaxF(&nmax[dst * H + h], s);
        }
    }
}

// ---------------- edge pass B: segment sum of exp (no writeback) ----------------
template<int H>
__global__ void edge_sum(const int* __restrict__ ei, const float* __restrict__ score,
                         const float* __restrict__ nmax, float* __restrict__ nsum) {
    int idx = blockIdx.x * blockDim.x + threadIdx.x;
    const int tot = ETOT * H;
    if (idx >= tot) return;
    int e = idx / H, h = idx - e * H;
    int dst = (e < N_EDGES) ? ei[N_EDGES + e] : (e - N_EDGES);
    float ex = __expf(score[idx] - nmax[dst * H + h]);
    atomicAdd(&nsum[dst * H + h], ex);
}

// ---------------- edge pass C: alpha * xl[src] scattered to dst ----------------
template<int H>
__global__ void edge_aggr(const float* __restrict__ xl, const int* __restrict__ ei,
                          const float* __restrict__ score, const float* __restrict__ nmax,
                          const float* __restrict__ nsum, float* __restrict__ out) {
    int w = (blockIdx.x * blockDim.x + threadIdx.x) >> 5;
    int lane = threadIdx.x & 31;
    if (w >= ETOT) return;
    int src, dst;
    if (w < N_EDGES) { src = ei[w]; dst = ei[N_EDGES + w]; }
    else             { src = dst = w - N_EDGES; }

    const int Wd = H * 128;
    const float4* xls = (const float4*)(xl + (size_t)src * Wd);
    float* ob = out + (size_t)dst * Wd;

#pragma unroll
    for (int h = 0; h < H; h++) {
        float ex = __expf(score[(size_t)w * H + h] - nmax[dst * H + h]);
        float alpha = ex / nsum[dst * H + h];
        float4 v = xls[h * 32 + lane];
        redAdd4(ob + h * 128 + lane * 4, alpha * v.x, alpha * v.y, alpha * v.z, alpha * v.w);
    }
}

// ---------------- bias + BN(eval) + ReLU, in place (layer 2 only) -------------
__global__ void bn_relu(float* __restrict__ h, const float* __restrict__ bias,
                        const float* __restrict__ g, const float* __restrict__ b,
                        const float* __restrict__ m, const float* __restrict__ v,
                        int total, int Wd) {
    int idx = blockIdx.x * blockDim.x + threadIdx.x;
    if (idx >= total) return;
    int c = idx % Wd;
    float val = h[idx] + bias[c];
    val = (val - m[c]) * rsqrtf(v[c] + BN_EPS) * g[c] + b[c];
    h[idx] = val > 0.f ? val : 0.f;
}

// ---------------- prediction head: one warp per pred edge ----------------
__global__ void head_kernel(const float* __restrict__ z, const int* __restrict__ pe,
                            const float* __restrict__ pr, const float* __restrict__ pert,
                            const float* __restrict__ Wp, const float* __restrict__ bp,
                            float* __restrict__ out) {
    __shared__ float sw[(W2 * 2 + 3) * 2];  // 1030 floats
    for (int i = threadIdx.x; i < (W2 * 2 + 3) * 2; i += blockDim.x) sw[i] = Wp[i];
    __syncthreads();

    int w = (blockIdx.x * blockDim.x + threadIdx.x) >> 5;
    int lane = threadIdx.x & 31;
    if (w >= N_PRED) return;
    int s = pe[w], d = pe[N_PRED + w];
    const float4* zs = (const float4*)(z + (size_t)s * W2);
    const float4* zd = (const float4*)(z + (size_t)d * W2);

    float a0 = 0.f, a1 = 0.f;
#pragma unroll
    for (int q = 0; q < 2; q++) {
        int r = lane * 2 + q;
        float4 vz = zs[r];
        int base = (r * 4) * 2;
        a0 += vz.x * sw[base] + vz.y * sw[base + 2] + vz.z * sw[base + 4] + vz.w * sw[base + 6];
        a1 += vz.x * sw[base + 1] + vz.y * sw[base + 3] + vz.z * sw[base + 5] + vz.w * sw[base + 7];
        float4 vd = zd[r];
        int base2 = (W2 + r * 4) * 2;
        a0 += vd.x * sw[base2] + vd.y * sw[base2 + 2] + vd.z * sw[base2 + 4] + vd.w * sw[base2 + 6];
        a1 += vd.x * sw[base2 + 1] + vd.y * sw[base2 + 3] + vd.z * sw[base2 + 5] + vd.w * sw[base2 + 7];
    }
    if (lane == 0) {
        float prs = pr[s], prd = pr[d], pp = pert[s] * pert[d];
        int b0 = (2 * W2) * 2;
        a0 += prs * sw[b0] + prd * sw[b0 + 2] + pp * sw[b0 + 4];
        a1 += prs * sw[b0 + 1] + prd * sw[b0 + 3] + pp * sw[b0 + 5];
    }
#pragma unroll
    for (int o = 16; o > 0; o >>= 1) {
        a0 += __shfl_xor_sync(0xFFFFFFFFu, a0, o);
        a1 += __shfl_xor_sync(0xFFFFFFFFu, a1, o);
    }
    if (lane == 0) {
        out[(size_t)w * 2 + 0] = a0 + bp[0];
        out[(size_t)w * 2 + 1] = a1 + bp[1];
    }
}

// ---------------- launch ----------------
extern "C" void kernel_launch(void* const* d_in, const int* in_sizes, int n_in,
                              void* d_out, int out_size) {
    const float* x     = (const float*)d_in[0];
    const int*   ei    = (const int*)d_in[1];
    const int*   pe    = (const int*)d_in[2];
    const float* pert  = (const float*)d_in[3];
    const float* pr    = (const float*)d_in[4];
    const float* Wl1   = (const float*)d_in[5];
    const float* bl1   = (const float*)d_in[6];
    const float* Wr1   = (const float*)d_in[7];
    const float* br1   = (const float*)d_in[8];
    const float* att1  = (const float*)d_in[9];
    const float* bias1 = (const float*)d_in[10];
    const float* bn1g  = (const float*)d_in[11];
    const float* bn1b  = (const float*)d_in[12];
    const float* bn1m  = (const float*)d_in[13];
    const float* bn1v  = (const float*)d_in[14];
    const float* Wl2   = (const float*)d_in[15];
    const float* bl2   = (const float*)d_in[16];
    const float* Wr2   = (const float*)d_in[17];
    const float* br2   = (const float*)d_in[18];
    const float* att2  = (const float*)d_in[19];
    const float* bias2 = (const float*)d_in[20];
    const float* bn2g  = (const float*)d_in[21];
    const float* bn2b  = (const float*)d_in[22];
    const float* bn2m  = (const float*)d_in[23];
    const float* bn2v  = (const float*)d_in[24];
    const float* Wp    = (const float*)d_in[25];
    const float* bp    = (const float*)d_in[26];
    float* out = (float*)d_out;

    float *xl1, *xr1, *agg1, *sc1, *nm1, *ns1;
    float *xl2, *xr2, *agg2, *sc2, *nm2, *ns2;
    float *bns1, *bnt1;
    cudaGetSymbolAddress((void**)&xl1, g_xl1);
    cudaGetSymbolAddress((void**)&xr1, g_xr1);
    cudaGetSymbolAddress((void**)&agg1, g_agg1);
    cudaGetSymbolAddress((void**)&sc1, g_score1);
    cudaGetSymbolAddress((void**)&nm1, g_nmax1);
    cudaGetSymbolAddress((void**)&ns1, g_nsum1);
    cudaGetSymbolAddress((void**)&xl2, g_xl2);
    cudaGetSymbolAddress((void**)&xr2, g_xr2);
    cudaGetSymbolAddress((void**)&agg2, g_agg2);
    cudaGetSymbolAddress((void**)&sc2, g_score2);
    cudaGetSymbolAddress((void**)&nm2, g_nmax2);
    cudaGetSymbolAddress((void**)&ns2, g_nsum2);
    cudaGetSymbolAddress((void**)&bns1, g_bns1);
    cudaGetSymbolAddress((void**)&bnt1, g_bnt1);

    const int TB = 256;
    int mblk = (N_NODES + GBM - 1) / GBM;        // 391
    int eblk = (ETOT * 32 + TB - 1) / TB;        // warp per edge

    bn_prep<<<(W1 + 255) / 256, 256>>>(bias1, bn1g, bn1b, bn1m, bn1v, bns1, bnt1, W1);

    // ---- layer 1 ----
    {
        dim3 g1(W1 / GBN, mblk);
        gemm_f2<false><<<g1, 256>>>(x, Wl1, bl1, xl1, N_NODES, 128, W1, nullptr, nullptr);
        gemm_f2<false><<<g1, 256>>>(x, Wr1, br1, xr1, N_NODES, 128, W1, nullptr, nullptr);
    }
    {
        int aggN = N_NODES * W1, nm = N_NODES * H1;
        init_layer<<<(aggN + TB - 1) / TB, TB>>>(agg1, aggN, nm1, ns1, nm);
    }
    edge_score<H1><<<eblk, TB>>>(xl1, xr1, att1, ei, sc1, nm1);
    {
        int tot = ETOT * H1;
        edge_sum<H1><<<(tot + TB - 1) / TB, TB>>>(ei, sc1, nm1, ns1);
    }
    edge_aggr<H1><<<eblk, TB>>>(xl1, ei, sc1, nm1, ns1, agg1);
    // NOTE: bias1 + BN1 + ReLU fused into layer-2 GEMM A-load (bns1/bnt1)

    // ---- layer 2 ----
    {
        dim3 g2(W2 / GBN, mblk);
        gemm_f2<true><<<g2, 256>>>(agg1, Wl2, bl2, xl2, N_NODES, W1, W2, bns1, bnt1);
        gemm_f2<true><<<g2, 256>>>(agg1, Wr2, br2, xr2, N_NODES, W1, W2, bns1, bnt1);
    }
    {
        int aggN = N_NODES * W2, nm = N_NODES * H2;
        init_layer<<<(aggN + TB - 1) / TB, TB>>>(agg2, aggN, nm2, ns2, nm);
    }
    edge_score<H2><<<eblk, TB>>>(xl2, xr2, att2, ei, sc2, nm2);
    {
        int tot = ETOT * H2;
        edge_sum<H2><<<(tot + TB - 1) / TB, TB>>>(ei, sc2, nm2, ns2);
    }
    edge_aggr<H2><<<eblk, TB>>>(xl2, ei, sc2, nm2, ns2, agg2);
    {
        int tot = N_NODES * W2;
        bn_relu<<<(tot + TB - 1) / TB, TB>>>(agg2, bias2, bn2g, bn2b, bn2m, bn2v, tot, W2);
    }

    // ---- head ----
    head_kernel<<<(N_PRED * 32 + TB - 1) / TB, TB>>>(agg2, pe, pr, pert, Wp, bp, out);
}

// round 3
// speedup vs baseline: 1.8256x; 1.4522x over previous
#include <cuda_runtime.h>
#include <math.h>

// ---------------- problem constants ----------------
#define N_NODES 50000
#define N_EDGES 600000
#define N_PRED  200000
#define ETOT    (N_EDGES + N_NODES)   // edges + self loops = 650000
#define W1      512                   // H1*HID
#define W2      256                   // H2*HID
#define H1      4
#define H2      2
#define BN_EPS  1e-5f

// ---------------- scratch (device globals; no allocation allowed) ----------------
__device__ float g_xl1[N_NODES * W1];
__device__ float g_xr1[N_NODES * W1];
__device__ float g_h1 [N_NODES * W1];   // layer-1 output after BN+ReLU
__device__ float g_xl2[N_NODES * W2];
__device__ float g_xr2[N_NODES * W2];
__device__ float g_z  [N_NODES * W2];   // layer-2 output after BN+ReLU

__device__ int g_deg[N_NODES];
__device__ int g_off[N_NODES + 1];
__device__ int g_cursor[N_NODES];
__device__ int g_csr_src[ETOT];

__device__ float g_bns1[W1];
__device__ float g_bnt1[W1];
__device__ float g_bns2[W2];
__device__ float g_bnt2[W2];

// ---------------- f32x2 helpers ----------------
__device__ __forceinline__ unsigned long long pk2(float x, float y) {
    unsigned long long r;
    asm("mov.b64 %0, {%1, %2};" : "=l"(r) : "f"(x), "f"(y));
    return r;
}
__device__ __forceinline__ void fma2(unsigned long long& c, unsigned long long a,
                                     unsigned long long b) {
    asm("fma.rn.f32x2 %0, %1, %2, %0;" : "+l"(c) : "l"(a), "l"(b));
}
__device__ __forceinline__ float2 upk2(unsigned long long u) {
    float2 f;
    asm("mov.b64 {%0, %1}, %2;" : "=f"(f.x), "=f"(f.y) : "l"(u));
    return f;
}

// ---------------- FFMA2 GEMM: C[M,Nn] = A[M,K] @ B[K,Nn] + bias ----------------
#define GBM 128
#define GBN 128
#define GBK 16

__global__ __launch_bounds__(256, 2)
void gemm_f2(const float* __restrict__ A, const float* __restrict__ B,
             const float* __restrict__ bias, float* __restrict__ C,
             int M, int K, int Nn) {
    __shared__ float As[2][GBK][GBM];
    __shared__ float Bs[2][GBK][GBN];
    int tid = threadIdx.x;
    int m0 = blockIdx.y * GBM;
    int n0 = blockIdx.x * GBN;

    int lrow = tid >> 1;
    int lkq  = (tid & 1) * 8;
    int bkr  = tid >> 4;
    int bnq  = (tid & 15) * 8;

    int tx = tid & 15;
    int ty = tid >> 4;
    int tx4 = tx * 4;
    int ty4 = ty * 4;

    unsigned long long acc[4][8];
#pragma unroll
    for (int p = 0; p < 4; p++)
#pragma unroll
        for (int j = 0; j < 8; j++) acc[p][j] = 0ull;

    float ar[8], br[8];
    int niter = K / GBK;

    auto loadA = [&](int k0) {
        int row = m0 + lrow;
        if (row < M) {
            float4 v0 = *(const float4*)(A + (size_t)row * K + k0 + lkq);
            float4 v1 = *(const float4*)(A + (size_t)row * K + k0 + lkq + 4);
            ar[0] = v0.x; ar[1] = v0.y; ar[2] = v0.z; ar[3] = v0.w;
            ar[4] = v1.x; ar[5] = v1.y; ar[6] = v1.z; ar[7] = v1.w;
        } else {
#pragma unroll
            for (int i = 0; i < 8; i++) ar[i] = 0.0f;
        }
    };
    auto loadB = [&](int k0) {
        const float4* p = (const float4*)(B + (size_t)(k0 + bkr) * Nn + n0 + bnq);
        float4 v0 = p[0], v1 = p[1];
        br[0] = v0.x; br[1] = v0.y; br[2] = v0.z; br[3] = v0.w;
        br[4] = v1.x; br[5] = v1.y; br[6] = v1.z; br[7] = v1.w;
    };
    auto stA = [&](int b) {
#pragma unroll
        for (int i = 0; i < 8; i++) As[b][lkq + i][lrow] = ar[i];
    };
    auto stB = [&](int b) {
        *(float4*)&Bs[b][bkr][bnq]     = make_float4(br[0], br[1], br[2], br[3]);
        *(float4*)&Bs[b][bkr][bnq + 4] = make_float4(br[4], br[5], br[6], br[7]);
    };

    loadA(0); loadB(0);
    stA(0);   stB(0);
    __syncthreads();

    for (int it = 0; it < niter; it++) {
        int cb = it & 1;
        if (it + 1 < niter) { loadA((it + 1) * GBK); loadB((it + 1) * GBK); }
#pragma unroll
        for (int k = 0; k < GBK; k++) {
            float4 a0 = *(const float4*)&As[cb][k][ty4];
            float4 a1 = *(const float4*)&As[cb][k][64 + ty4];
            float4 b0 = *(const float4*)&Bs[cb][k][tx4];
            float4 b1 = *(const float4*)&Bs[cb][k][64 + tx4];
            unsigned long long aa[4], bb[8];
            aa[0] = pk2(a0.x, a0.y); aa[1] = pk2(a0.z, a0.w);
            aa[2] = pk2(a1.x, a1.y); aa[3] = pk2(a1.z, a1.w);
            bb[0] = pk2(b0.x, b0.x); bb[1] = pk2(b0.y, b0.y);
            bb[2] = pk2(b0.z, b0.z); bb[3] = pk2(b0.w, b0.w);
            bb[4] = pk2(b1.x, b1.x); bb[5] = pk2(b1.y, b1.y);
            bb[6] = pk2(b1.z, b1.z); bb[7] = pk2(b1.w, b1.w);
#pragma unroll
            for (int p = 0; p < 4; p++)
#pragma unroll
                for (int j = 0; j < 8; j++)
                    fma2(acc[p][j], aa[p], bb[j]);
        }
        if (it + 1 < niter) { stA(cb ^ 1); stB(cb ^ 1); __syncthreads(); }
    }

    float4 bi0 = *(const float4*)(bias + n0 + tx4);
    float4 bi1 = *(const float4*)(bias + n0 + 64 + tx4);
#pragma unroll
    for (int p = 0; p < 4; p++) {
        int rbase = (p < 2) ? (m0 + ty4 + 2 * p) : (m0 + 64 + ty4 + 2 * (p - 2));
        float2 v[8];
#pragma unroll
        for (int j = 0; j < 8; j++) v[j] = upk2(acc[p][j]);
        if (rbase < M) {
            float4 o0 = make_float4(v[0].x + bi0.x, v[1].x + bi0.y, v[2].x + bi0.z, v[3].x + bi0.w);
            float4 o1 = make_float4(v[4].x + bi1.x, v[5].x + bi1.y, v[6].x + bi1.z, v[7].x + bi1.w);
            *(float4*)(C + (size_t)rbase * Nn + n0 + tx4)      = o0;
            *(float4*)(C + (size_t)rbase * Nn + n0 + 64 + tx4) = o1;
        }
        if (rbase + 1 < M) {
            float4 o0 = make_float4(v[0].y + bi0.x, v[1].y + bi0.y, v[2].y + bi0.z, v[3].y + bi0.w);
            float4 o1 = make_float4(v[4].y + bi1.x, v[5].y + bi1.y, v[6].y + bi1.z, v[7].y + bi1.w);
            *(float4*)(C + (size_t)(rbase + 1) * Nn + n0 + tx4)      = o0;
            *(float4*)(C + (size_t)(rbase + 1) * Nn + n0 + 64 + tx4) = o1;
        }
    }
}

// ---------------- BN prep: fold GAT bias + eval BN into scale/shift ------------
__global__ void bn_prep(const float* __restrict__ bias, const float* __restrict__ g,
                        const float* __restrict__ b, const float* __restrict__ m,
                        const float* __restrict__ v, float* __restrict__ s,
                        float* __restrict__ t, int n) {
    int i = blockIdx.x * blockDim.x + threadIdx.x;
    if (i < n) {
        float sc = g[i] * rsqrtf(v[i] + BN_EPS);
        s[i] = sc;
        t[i] = b[i] + (bias[i] - m[i]) * sc;
    }
}

// ---------------- CSR build ----------------
__global__ void deg_zero(int* deg) {
    int i = blockIdx.x * blockDim.x + threadIdx.x;
    if (i < N_NODES) deg[i] = 0;
}

__global__ void deg_hist(const int* __restrict__ ei, int* __restrict__ deg) {
    int i = blockIdx.x * blockDim.x + threadIdx.x;
    if (i >= ETOT) return;
    int dst = (i < N_EDGES) ? ei[N_EDGES + i] : (i - N_EDGES);
    atomicAdd(&deg[dst], 1);
}

__global__ void scan_kernel(const int* __restrict__ deg, int* __restrict__ off,
                            int* __restrict__ cursor) {
    __shared__ int warp_sums[32];
    const int T = 1024;
    int tid = threadIdx.x;
    int chunk = (N_NODES + T - 1) / T;
    int start = tid * chunk;
    int end = min(start + chunk, N_NODES);
    int local = 0;
    for (int i = start; i < end; i++) local += deg[i];
    int lane = tid & 31, wid = tid >> 5;
    int v = local;
#pragma unroll
    for (int o = 1; o < 32; o <<= 1) {
        int u = __shfl_up_sync(0xFFFFFFFFu, v, o);
        if (lane >= o) v += u;
    }
    if (lane == 31) warp_sums[wid] = v;
    __syncthreads();
    if (wid == 0) {
        int s = warp_sums[lane];
#pragma unroll
        for (int o = 1; o < 32; o <<= 1) {
            int u = __shfl_up_sync(0xFFFFFFFFu, s, o);
            if (lane >= o) s += u;
        }
        warp_sums[lane] = s;
    }
    __syncthreads();
    int excl = v - local + (wid > 0 ? warp_sums[wid - 1] : 0);
    int run = excl;
    for (int i = start; i < end; i++) {
        off[i] = run;
        cursor[i] = run;
        run += deg[i];
    }
    if (tid == T - 1) off[N_NODES] = run;
}

__global__ void csr_scatter(const int* __restrict__ ei, int* __restrict__ cursor,
                            int* __restrict__ csr_src) {
    int i = blockIdx.x * blockDim.x + threadIdx.x;
    if (i >= ETOT) return;
    int src, dst;
    if (i < N_EDGES) { src = ei[i]; dst = ei[N_EDGES + i]; }
    else             { src = dst = i - N_EDGES; }
    int pos = atomicAdd(&cursor[dst], 1);
    csr_src[pos] = src;
}

// ---------------- fused GATv2 aggregation (one warp per dst node) --------------
// online softmax over in-edges; output = relu(bn_scale * (acc/sum) + bn_shift)
template<int H>
__global__ __launch_bounds__(256)
void fused_agg(const float* __restrict__ xl, const float* __restrict__ xr,
               const float* __restrict__ att,
               const int* __restrict__ off, const int* __restrict__ csr_src,
               const float* __restrict__ bns, const float* __restrict__ bnt,
               float* __restrict__ out) {
    int node = (blockIdx.x * blockDim.x + threadIdx.x) >> 5;
    int lane = threadIdx.x & 31;
    if (node >= N_NODES) return;
    const int Wd = H * 128;

    const float4* xr4 = (const float4*)(xr + (size_t)node * Wd);
    const float4* at4 = (const float4*)att;

    float4 xrr[H], attr[H], acc[H];
    float m[H], sum[H];
#pragma unroll
    for (int h = 0; h < H; h++) {
        xrr[h]  = xr4[h * 32 + lane];
        attr[h] = at4[h * 32 + lane];
        acc[h]  = make_float4(0.f, 0.f, 0.f, 0.f);
        m[h]    = -INFINITY;
        sum[h]  = 0.f;
    }

    int e0 = off[node], e1 = off[node + 1];
    int src = csr_src[e0];
    float4 v[H];
    {
        const float4* xs = (const float4*)(xl + (size_t)src * Wd);
#pragma unroll
        for (int h = 0; h < H; h++) v[h] = xs[h * 32 + lane];
    }

    for (int e = e0; e < e1; e++) {
        // prefetch next edge's features
        int nsrc = (e + 1 < e1) ? csr_src[e + 1] : src;
        const float4* xn = (const float4*)(xl + (size_t)nsrc * Wd);
        float4 vn[H];
#pragma unroll
        for (int h = 0; h < H; h++) vn[h] = xn[h * 32 + lane];

#pragma unroll
        for (int h = 0; h < H; h++) {
            float ex = v[h].x + xrr[h].x; ex = ex > 0.f ? ex : 0.2f * ex;
            float ey = v[h].y + xrr[h].y; ey = ey > 0.f ? ey : 0.2f * ey;
            float ez = v[h].z + xrr[h].z; ez = ez > 0.f ? ez : 0.2f * ez;
            float ew = v[h].w + xrr[h].w; ew = ew > 0.f ? ew : 0.2f * ew;
            float s = ex * attr[h].x + ey * attr[h].y + ez * attr[h].z + ew * attr[h].w;
#pragma unroll
            for (int o = 16; o > 0; o >>= 1) s += __shfl_xor_sync(0xFFFFFFFFu, s, o);

            float mn = fmaxf(m[h], s);
            float c  = __expf(m[h] - mn);
            float p  = __expf(s - mn);
            sum[h]   = sum[h] * c + p;
            acc[h].x = acc[h].x * c + p * v[h].x;
            acc[h].y = acc[h].y * c + p * v[h].y;
            acc[h].z = acc[h].z * c + p * v[h].z;
            acc[h].w = acc[h].w * c + p * v[h].w;
            m[h] = mn;
        }
#pragma unroll
        for (int h = 0; h < H; h++) v[h] = vn[h];
    }

#pragma unroll
    for (int h = 0; h < H; h++) {
        int cbase = h * 128 + lane * 4;
        float4 sc = *(const float4*)(bns + cbase);
        float4 tt = *(const float4*)(bnt + cbase);
        float inv = 1.f / sum[h];
        float4 o;
        o.x = fmaxf(fmaf(acc[h].x * inv, sc.x, tt.x), 0.f);
        o.y = fmaxf(fmaf(acc[h].y * inv, sc.y, tt.y), 0.f);
        o.z = fmaxf(fmaf(acc[h].z * inv, sc.z, tt.z), 0.f);
        o.w = fmaxf(fmaf(acc[h].w * inv, sc.w, tt.w), 0.f);
        *(float4*)(out + (size_t)node * Wd + cbase) = o;
    }
}

// ---------------- prediction head: one warp per pred edge ----------------
__global__ void head_kernel(const float* __restrict__ z, const int* __restrict__ pe,
                            const float* __restrict__ pr, const float* __restrict__ pert,
                            const float* __restrict__ Wp, const float* __restrict__ bp,
                            float* __restrict__ out) {
    __shared__ float sw[(W2 * 2 + 3) * 2];
    for (int i = threadIdx.x; i < (W2 * 2 + 3) * 2; i += blockDim.x) sw[i] = Wp[i];
    __syncthreads();

    int w = (blockIdx.x * blockDim.x + threadIdx.x) >> 5;
    int lane = threadIdx.x & 31;
    if (w >= N_PRED) return;
    int s = pe[w], d = pe[N_PRED + w];
    const float4* zs = (const float4*)(z + (size_t)s * W2);
    const float4* zd = (const float4*)(z + (size_t)d * W2);

    float a0 = 0.f, a1 = 0.f;
#pragma unroll
    for (int q = 0; q < 2; q++) {
        int r = lane * 2 + q;
        float4 vz = zs[r];
        int base = (r * 4) * 2;
        a0 += vz.x * sw[base] + vz.y * sw[base + 2] + vz.z * sw[base + 4] + vz.w * sw[base + 6];
        a1 += vz.x * sw[base + 1] + vz.y * sw[base + 3] + vz.z * sw[base + 5] + vz.w * sw[base + 7];
        float4 vd = zd[r];
        int base2 = (W2 + r * 4) * 2;
        a0 += vd.x * sw[base2] + vd.y * sw[base2 + 2] + vd.z * sw[base2 + 4] + vd.w * sw[base2 + 6];
        a1 += vd.x * sw[base2 + 1] + vd.y * sw[base2 + 3] + vd.z * sw[base2 + 5] + vd.w * sw[base2 + 7];
    }
    if (lane == 0) {
        float prs = pr[s], prd = pr[d], pp = pert[s] * pert[d];
        int b0 = (2 * W2) * 2;
        a0 += prs * sw[b0] + prd * sw[b0 + 2] + pp * sw[b0 + 4];
        a1 += prs * sw[b0 + 1] + prd * sw[b0 + 3] + pp * sw[b0 + 5];
    }
#pragma unroll
    for (int o = 16; o > 0; o >>= 1) {
        a0 += __shfl_xor_sync(0xFFFFFFFFu, a0, o);
        a1 += __shfl_xor_sync(0xFFFFFFFFu, a1, o);
    }
    if (lane == 0) {
        out[(size_t)w * 2 + 0] = a0 + bp[0];
        out[(size_t)w * 2 + 1] = a1 + bp[1];
    }
}

// ---------------- launch ----------------
extern "C" void kernel_launch(void* const* d_in, const int* in_sizes, int n_in,
                              void* d_out, int out_size) {
    const float* x     = (const float*)d_in[0];
    const int*   ei    = (const int*)d_in[1];
    const int*   pe    = (const int*)d_in[2];
    const float* pert  = (const float*)d_in[3];
    const float* pr    = (const float*)d_in[4];
    const float* Wl1   = (const float*)d_in[5];
    const float* bl1   = (const float*)d_in[6];
    const float* Wr1   = (const float*)d_in[7];
    const float* br1   = (const float*)d_in[8];
    const float* att1  = (const float*)d_in[9];
    const float* bias1 = (const float*)d_in[10];
    const float* bn1g  = (const float*)d_in[11];
    const float* bn1b  = (const float*)d_in[12];
    const float* bn1m  = (const float*)d_in[13];
    const float* bn1v  = (const float*)d_in[14];
    const float* Wl2   = (const float*)d_in[15];
    const float* bl2   = (const float*)d_in[16];
    const float* Wr2   = (const float*)d_in[17];
    const float* br2   = (const float*)d_in[18];
    const float* att2  = (const float*)d_in[19];
    const float* bias2 = (const float*)d_in[20];
    const float* bn2g  = (const float*)d_in[21];
    const float* bn2b  = (const float*)d_in[22];
    const float* bn2m  = (const float*)d_in[23];
    const float* bn2v  = (const float*)d_in[24];
    const float* Wp    = (const float*)d_in[25];
    const float* bp    = (const float*)d_in[26];
    float* out = (float*)d_out;

    float *xl1, *xr1, *h1, *xl2, *xr2, *z;
    float *bns1, *bnt1, *bns2, *bnt2;
    int *deg, *off, *cursor, *csr_src;
    cudaGetSymbolAddress((void**)&xl1, g_xl1);
    cudaGetSymbolAddress((void**)&xr1, g_xr1);
    cudaGetSymbolAddress((void**)&h1,  g_h1);
    cudaGetSymbolAddress((void**)&xl2, g_xl2);
    cudaGetSymbolAddress((void**)&xr2, g_xr2);
    cudaGetSymbolAddress((void**)&z,   g_z);
    cudaGetSymbolAddress((void**)&bns1, g_bns1);
    cudaGetSymbolAddress((void**)&bnt1, g_bnt1);
    cudaGetSymbolAddress((void**)&bns2, g_bns2);
    cudaGetSymbolAddress((void**)&bnt2, g_bnt2);
    cudaGetSymbolAddress((void**)&deg, g_deg);
    cudaGetSymbolAddress((void**)&off, g_off);
    cudaGetSymbolAddress((void**)&cursor, g_cursor);
    cudaGetSymbolAddress((void**)&csr_src, g_csr_src);

    const int TB = 256;
    int mblk = (N_NODES + GBM - 1) / GBM;
    int nwarp_blk = (N_NODES * 32 + TB - 1) / TB;

    // ---- CSR build (graph shared by both layers) ----
    deg_zero<<<(N_NODES + TB - 1) / TB, TB>>>(deg);
    deg_hist<<<(ETOT + TB - 1) / TB, TB>>>(ei, deg);
    scan_kernel<<<1, 1024>>>(deg, off, cursor);
    csr_scatter<<<(ETOT + TB - 1) / TB, TB>>>(ei, cursor, csr_src);

    // ---- BN folding ----
    bn_prep<<<(W1 + 255) / 256, 256>>>(bias1, bn1g, bn1b, bn1m, bn1v, bns1, bnt1, W1);
    bn_prep<<<(W2 + 255) / 256, 256>>>(bias2, bn2g, bn2b, bn2m, bn2v, bns2, bnt2, W2);

    // ---- layer 1 ----
    {
        dim3 g1(W1 / GBN, mblk);
        gemm_f2<<<g1, 256>>>(x, Wl1, bl1, xl1, N_NODES, 128, W1);
        gemm_f2<<<g1, 256>>>(x, Wr1, br1, xr1, N_NODES, 128, W1);
    }
    fused_agg<H1><<<nwarp_blk, TB>>>(xl1, xr1, att1, off, csr_src, bns1, bnt1, h1);

    // ---- layer 2 ----
    {
        dim3 g2(W2 / GBN, mblk);
        gemm_f2<<<g2, 256>>>(h1, Wl2, bl2, xl2, N_NODES, W1, W2);
        gemm_f2<<<g2, 256>>>(h1, Wr2, br2, xr2, N_NODES, W1, W2);
    }
    fused_agg<H2><<<nwarp_blk, TB>>>(xl2, xr2, att2, off, csr_src, bns2, bnt2, z);

    // ---- head ----
    head_kernel<<<(N_PRED * 32 + TB - 1) / TB, TB>>>(z, pe, pr, pert, Wp, bp, out);
}

// round 5
// speedup vs baseline: 2.5110x; 1.3754x over previous
#include <cuda_runtime.h>
#include <cuda_bf16.h>
#include <math.h>
#include <cstdint>

// ---------------- problem constants ----------------
#define N_NODES 50000
#define N_EDGES 600000
#define N_PRED  200000
#define ETOT    (N_EDGES + N_NODES)
#define W1      512
#define W2      256
#define H1      4
#define H2      2
#define K1      128
#define K1S     384      // 3*K1 split width
#define K2      512
#define K2S     1536     // 3*K2 split width
#define BN_EPS  1e-5f

// ---------------- scratch (device globals) ----------------
__device__ float g_xl1[N_NODES * W1];
__device__ float g_xr1[N_NODES * W1];
__device__ float g_h1 [N_NODES * W1];
__device__ float g_xl2[N_NODES * W2];
__device__ float g_xr2[N_NODES * W2];
__device__ float g_z  [N_NODES * W2];

__device__ __nv_bfloat16 g_As1[(size_t)N_NODES * K1S];
__device__ __nv_bfloat16 g_As2[(size_t)N_NODES * K2S];
__device__ __nv_bfloat16 g_Wl1s[W1 * K1S];
__device__ __nv_bfloat16 g_Wr1s[W1 * K1S];
__device__ __nv_bfloat16 g_Wl2s[W2 * K2S];
__device__ __nv_bfloat16 g_Wr2s[W2 * K2S];

__device__ int g_deg[N_NODES];
__device__ int g_off[N_NODES + 1];
__device__ int g_cursor[N_NODES];
__device__ int g_csr_src[ETOT];

__device__ float g_bns1[W1];
__device__ float g_bnt1[W1];
__device__ float g_bns2[W2];
__device__ float g_bnt2[W2];

// ---------------- helpers ----------------
__device__ __forceinline__ uint32_t smem_to_u32(const void* p) {
    uint32_t a;
    asm("{ .reg .u64 t; cvta.to.shared.u64 t, %1; cvt.u32.u64 %0, t; }" : "=r"(a) : "l"(p));
    return a;
}
#define SWZ128(b) ((b) ^ (((b) >> 3) & 0x70))

__device__ __forceinline__ void ldmatrix_x4(uint32_t* r, uint32_t addr) {
    asm volatile("ldmatrix.sync.aligned.m8n8.x4.shared.b16 {%0,%1,%2,%3}, [%4];"
                 : "=r"(r[0]), "=r"(r[1]), "=r"(r[2]), "=r"(r[3]) : "r"(addr));
}
__device__ __forceinline__ void mma16816(float* c, const uint32_t* a,
                                         uint32_t b0, uint32_t b1) {
    asm volatile("mma.sync.aligned.m16n8k16.row.col.f32.bf16.bf16.f32 "
                 "{%0,%1,%2,%3}, {%4,%5,%6,%7}, {%8,%9}, {%0,%1,%2,%3};"
                 : "+f"(c[0]), "+f"(c[1]), "+f"(c[2]), "+f"(c[3])
                 : "r"(a[0]), "r"(a[1]), "r"(a[2]), "r"(a[3]), "r"(b0), "r"(b1));
}

// ---------------- split-prep kernels ----------------
// A'' [M, 3K] = [a0 | a1 | a0]
__global__ void split_A(const float* __restrict__ X, __nv_bfloat16* __restrict__ out,
                        int M, int K) {
    int idx = blockIdx.x * blockDim.x + threadIdx.x;
    if (idx >= M * K) return;
    int m = idx / K, k = idx - m * K;
    float a = X[idx];
    __nv_bfloat16 a0 = __float2bfloat16(a);
    __nv_bfloat16 a1 = __float2bfloat16(a - __bfloat162float(a0));
    size_t base = (size_t)m * (3 * K);
    out[base + k] = a0;
    out[base + K + k] = a1;
    out[base + 2 * K + k] = a0;
}

// B'' [Nn, 3K] from W [K, Nn]: [b0 | b0 | b1]
__global__ void split_W(const float* __restrict__ W, __nv_bfloat16* __restrict__ out,
                        int K, int Nn) {
    int idx = blockIdx.x * blockDim.x + threadIdx.x;
    if (idx >= K * Nn) return;
    int k = idx / Nn, n = idx - k * Nn;
    float b = W[idx];
    __nv_bfloat16 b0 = __float2bfloat16(b);
    __nv_bfloat16 b1 = __float2bfloat16(b - __bfloat162float(b0));
    size_t base = (size_t)n * (3 * K);
    out[base + k] = b0;
    out[base + K + k] = b0;
    out[base + 2 * K + k] = b1;
}

// ---------------- HMMA bf16 GEMM ----------------
// C[M,Nn] = A''[M,Ks] @ B''[Nn,Ks]^T + bias
// tile 128x128, K-chunk 64 bf16, 8 warps (4x2), mma.sync m16n8k16, cp.async 2-stage.
#define STAGE_BYTES 32768   // 16KB A + 16KB B per stage

__global__ __launch_bounds__(256)
void gemm_mma(const __nv_bfloat16* __restrict__ A, const __nv_bfloat16* __restrict__ B,
              const float* __restrict__ bias, float* __restrict__ C,
              int M, int Ks, int Nn) {
    extern __shared__ __align__(1024) char sm[];
    int tid = threadIdx.x;
    int wid = tid >> 5, lane = tid & 31;
    int m0 = blockIdx.y * 128, n0 = blockIdx.x * 128;
    int wm = wid >> 1, wn = wid & 1;   // warp tile: rows 32*wm, cols 64*wn
    uint32_t smb = smem_to_u32(sm);

    float acc[2][8][4];
#pragma unroll
    for (int t = 0; t < 2; t++)
#pragma unroll
        for (int j = 0; j < 8; j++)
#pragma unroll
            for (int q = 0; q < 4; q++) acc[t][j][q] = 0.f;

    int nch = Ks / 64;

    auto issue_load = [&](int c, int s) {
        uint32_t base = smb + s * STAGE_BYTES;
#pragma unroll
        for (int r = 0; r < 4; r++) {
            int idx = tid + r * 256;
            int row = idx >> 3, j = idx & 7;
            const __nv_bfloat16* gp = A + (size_t)(m0 + row) * Ks + c * 64 + j * 8;
            uint32_t sa = base + SWZ128(row * 128 + j * 16);
            int sz = (m0 + row < M) ? 16 : 0;
            asm volatile("cp.async.cg.shared.global [%0], [%1], 16, %2;"
                         :: "r"(sa), "l"(gp), "r"(sz));
        }
#pragma unroll
        for (int r = 0; r < 4; r++) {
            int idx = tid + r * 256;
            int row = idx >> 3, j = idx & 7;
            const __nv_bfloat16* gp = B + (size_t)(n0 + row) * Ks + c * 64 + j * 8;
            uint32_t sa = base + 16384 + SWZ128(row * 128 + j * 16);
            asm volatile("cp.async.cg.shared.global [%0], [%1], 16;"
                         :: "r"(sa), "l"(gp));
        }
        asm volatile("cp.async.commit_group;");
    };

    issue_load(0, 0);

    for (int c = 0; c < nch; c++) {
        asm volatile("cp.async.wait_group 0;");
        __syncthreads();
        if (c + 1 < nch) issue_load(c + 1, (c + 1) & 1);

        uint32_t ab = smb + (c & 1) * STAGE_BYTES;
        uint32_t bb = ab + 16384;
#pragma unroll
        for (int kk = 0; kk < 4; kk++) {
            uint32_t af[2][4];
#pragma unroll
            for (int t = 0; t < 2; t++) {
                int rl = 32 * wm + 16 * t + (lane & 15);
                uint32_t ad = ab + SWZ128(rl * 128 + kk * 32 + (lane >> 4) * 16);
                ldmatrix_x4(af[t], ad);
            }
            uint32_t bf[4][4];
#pragma unroll
            for (int p = 0; p < 4; p++) {
                int nl = 64 * wn + 16 * p + ((lane >> 4) << 3) + (lane & 7);
                uint32_t bd = bb + SWZ128(nl * 128 + kk * 32 + ((lane >> 3) & 1) * 16);
                ldmatrix_x4(bf[p], bd);
            }
#pragma unroll
            for (int t = 0; t < 2; t++)
#pragma unroll
                for (int j = 0; j < 8; j++)
                    mma16816(acc[t][j], af[t],
                             bf[j >> 1][(j & 1) * 2], bf[j >> 1][(j & 1) * 2 + 1]);
        }
    }

    // epilogue: fp32 accums + bias -> C
#pragma unroll
    for (int t = 0; t < 2; t++) {
        int gr = m0 + 32 * wm + 16 * t + (lane >> 2);
#pragma unroll
        for (int j = 0; j < 8; j++) {
            int gc = n0 + 64 * wn + 8 * j + (lane & 3) * 2;
            float2 bi = *(const float2*)(bias + gc);
            if (gr < M) {
                float2 o = make_float2(acc[t][j][0] + bi.x, acc[t][j][1] + bi.y);
                *(float2*)(C + (size_t)gr * Nn + gc) = o;
            }
            if (gr + 8 < M) {
                float2 o = make_float2(acc[t][j][2] + bi.x, acc[t][j][3] + bi.y);
                *(float2*)(C + (size_t)(gr + 8) * Nn + gc) = o;
            }
        }
    }
}

// ---------------- BN prep ----------------
__global__ void bn_prep(const float* __restrict__ bias, const float* __restrict__ g,
                        const float* __restrict__ b, const float* __restrict__ m,
                        const float* __restrict__ v, float* __restrict__ s,
                        float* __restrict__ t, int n) {
    int i = blockIdx.x * blockDim.x + threadIdx.x;
    if (i < n) {
        float sc = g[i] * rsqrtf(v[i] + BN_EPS);
        s[i] = sc;
        t[i] = b[i] + (bias[i] - m[i]) * sc;
    }
}

// ---------------- CSR build ----------------
__global__ void deg_zero(int* deg) {
    int i = blockIdx.x * blockDim.x + threadIdx.x;
    if (i < N_NODES) deg[i] = 0;
}
__global__ void deg_hist(const int* __restrict__ ei, int* __restrict__ deg) {
    int i = blockIdx.x * blockDim.x + threadIdx.x;
    if (i >= ETOT) return;
    int dst = (i < N_EDGES) ? ei[N_EDGES + i] : (i - N_EDGES);
    atomicAdd(&deg[dst], 1);
}
__global__ void scan_kernel(const int* __restrict__ deg, int* __restrict__ off,
                            int* __restrict__ cursor) {
    __shared__ int warp_sums[32];
    const int T = 1024;
    int tid = threadIdx.x;
    int chunk = (N_NODES + T - 1) / T;
    int start = tid * chunk;
    int end = min(start + chunk, N_NODES);
    int local = 0;
    for (int i = start; i < end; i++) local += deg[i];
    int lane = tid & 31, wid = tid >> 5;
    int v = local;
#pragma unroll
    for (int o = 1; o < 32; o <<= 1) {
        int u = __shfl_up_sync(0xFFFFFFFFu, v, o);
        if (lane >= o) v += u;
    }
    if (lane == 31) warp_sums[wid] = v;
    __syncthreads();
    if (wid == 0) {
        int s = warp_sums[lane];
#pragma unroll
        for (int o = 1; o < 32; o <<= 1) {
            int u = __shfl_up_sync(0xFFFFFFFFu, s, o);
            if (lane >= o) s += u;
        }
        warp_sums[lane] = s;
    }
    __syncthreads();
    int excl = v - local + (wid > 0 ? warp_sums[wid - 1] : 0);
    int run = excl;
    for (int i = start; i < end; i++) {
        off[i] = run;
        cursor[i] = run;
        run += deg[i];
    }
    if (tid == T - 1) off[N_NODES] = run;
}
__global__ void csr_scatter(const int* __restrict__ ei, int* __restrict__ cursor,
                            int* __restrict__ csr_src) {
    int i = blockIdx.x * blockDim.x + threadIdx.x;
    if (i >= ETOT) return;
    int src, dst;
    if (i < N_EDGES) { src = ei[i]; dst = ei[N_EDGES + i]; }
    else             { src = dst = i - N_EDGES; }
    int pos = atomicAdd(&cursor[dst], 1);
    csr_src[pos] = src;
}

// ---------------- fused GATv2 aggregation (one warp per dst node) --------------
template<int H>
__global__ __launch_bounds__(256)
void fused_agg(const float* __restrict__ xl, const float* __restrict__ xr,
               const float* __restrict__ att,
               const int* __restrict__ off, const int* __restrict__ csr_src,
               const float* __restrict__ bns, const float* __restrict__ bnt,
               float* __restrict__ out) {
    int node = (blockIdx.x * blockDim.x + threadIdx.x) >> 5;
    int lane = threadIdx.x & 31;
    if (node >= N_NODES) return;
    const int Wd = H * 128;

    const float4* xr4 = (const float4*)(xr + (size_t)node * Wd);
    const float4* at4 = (const float4*)att;

    float4 xrr[H], attr[H], acc[H];
    float m[H], sum[H];
#pragma unroll
    for (int h = 0; h < H; h++) {
        xrr[h]  = xr4[h * 32 + lane];
        attr[h] = at4[h * 32 + lane];
        acc[h]  = make_float4(0.f, 0.f, 0.f, 0.f);
        m[h]    = -INFINITY;
        sum[h]  = 0.f;
    }

    int e0 = off[node], e1 = off[node + 1];
    int src = csr_src[e0];
    float4 v[H];
    {
        const float4* xs = (const float4*)(xl + (size_t)src * Wd);
#pragma unroll
        for (int h = 0; h < H; h++) v[h] = xs[h * 32 + lane];
    }

    for (int e = e0; e < e1; e++) {
        int nsrc = (e + 1 < e1) ? csr_src[e + 1] : src;
        const float4* xn = (const float4*)(xl + (size_t)nsrc * Wd);
        float4 vn[H];
#pragma unroll
        for (int h = 0; h < H; h++) vn[h] = xn[h * 32 + lane];

#pragma unroll
        for (int h = 0; h < H; h++) {
            float ex = v[h].x + xrr[h].x; ex = ex > 0.f ? ex : 0.2f * ex;
            float ey = v[h].y + xrr[h].y; ey = ey > 0.f ? ey : 0.2f * ey;
            float ez = v[h].z + xrr[h].z; ez = ez > 0.f ? ez : 0.2f * ez;
            float ew = v[h].w + xrr[h].w; ew = ew > 0.f ? ew : 0.2f * ew;
            float s = ex * attr[h].x + ey * attr[h].y + ez * attr[h].z + ew * attr[h].w;
#pragma unroll
            for (int o = 16; o > 0; o >>= 1) s += __shfl_xor_sync(0xFFFFFFFFu, s, o);

            float mn = fmaxf(m[h], s);
            float c  = __expf(m[h] - mn);
            float p  = __expf(s - mn);
            sum[h]   = sum[h] * c + p;
            acc[h].x = acc[h].x * c + p * v[h].x;
            acc[h].y = acc[h].y * c + p * v[h].y;
            acc[h].z = acc[h].z * c + p * v[h].z;
            acc[h].w = acc[h].w * c + p * v[h].w;
            m[h] = mn;
        }
#pragma unroll
        for (int h = 0; h < H; h++) v[h] = vn[h];
    }

#pragma unroll
    for (int h = 0; h < H; h++) {
        int cbase = h * 128 + lane * 4;
        float4 sc = *(const float4*)(bns + cbase);
        float4 tt = *(const float4*)(bnt + cbase);
        float inv = 1.f / sum[h];
        float4 o;
        o.x = fmaxf(fmaf(acc[h].x * inv, sc.x, tt.x), 0.f);
        o.y = fmaxf(fmaf(acc[h].y * inv, sc.y, tt.y), 0.f);
        o.z = fmaxf(fmaf(acc[h].z * inv, sc.z, tt.z), 0.f);
        o.w = fmaxf(fmaf(acc[h].w * inv, sc.w, tt.w), 0.f);
        *(float4*)(out + (size_t)node * Wd + cbase) = o;
    }
}

// ---------------- prediction head ----------------
__global__ void head_kernel(const float* __restrict__ z, const int* __restrict__ pe,
                            const float* __restrict__ pr, const float* __restrict__ pert,
                            const float* __restrict__ Wp, const float* __restrict__ bp,
                            float* __restrict__ out) {
    __shared__ float sw[(W2 * 2 + 3) * 2];
    for (int i = threadIdx.x; i < (W2 * 2 + 3) * 2; i += blockDim.x) sw[i] = Wp[i];
    __syncthreads();

    int w = (blockIdx.x * blockDim.x + threadIdx.x) >> 5;
    int lane = threadIdx.x & 31;
    if (w >= N_PRED) return;
    int s = pe[w], d = pe[N_PRED + w];
    const float4* zs = (const float4*)(z + (size_t)s * W2);
    const float4* zd = (const float4*)(z + (size_t)d * W2);

    float a0 = 0.f, a1 = 0.f;
#pragma unroll
    for (int q = 0; q < 2; q++) {
        int r = lane * 2 + q;
        float4 vz = zs[r];
        int base = (r * 4) * 2;
        a0 += vz.x * sw[base] + vz.y * sw[base + 2] + vz.z * sw[base + 4] + vz.w * sw[base + 6];
        a1 += vz.x * sw[base + 1] + vz.y * sw[base + 3] + vz.z * sw[base + 5] + vz.w * sw[base + 7];
        float4 vd = zd[r];
        int base2 = (W2 + r * 4) * 2;
        a0 += vd.x * sw[base2] + vd.y * sw[base2 + 2] + vd.z * sw[base2 + 4] + vd.w * sw[base2 + 6];
        a1 += vd.x * sw[base2 + 1] + vd.y * sw[base2 + 3] + vd.z * sw[base2 + 5] + vd.w * sw[base2 + 7];
    }
    if (lane == 0) {
        float prs = pr[s], prd = pr[d], pp = pert[s] * pert[d];
        int b0 = (2 * W2) * 2;
        a0 += prs * sw[b0] + prd * sw[b0 + 2] + pp * sw[b0 + 4];
        a1 += prs * sw[b0 + 1] + prd * sw[b0 + 3] + pp * sw[b0 + 5];
    }
#pragma unroll
    for (int o = 16; o > 0; o >>= 1) {
        a0 += __shfl_xor_sync(0xFFFFFFFFu, a0, o);
        a1 += __shfl_xor_sync(0xFFFFFFFFu, a1, o);
    }
    if (lane == 0) {
        out[(size_t)w * 2 + 0] = a0 + bp[0];
        out[(size_t)w * 2 + 1] = a1 + bp[1];
    }
}

// ---------------- launch ----------------
extern "C" void kernel_launch(void* const* d_in, const int* in_sizes, int n_in,
                              void* d_out, int out_size) {
    const float* x     = (const float*)d_in[0];
    const int*   ei    = (const int*)d_in[1];
    const int*   pe    = (const int*)d_in[2];
    const float* pert  = (const float*)d_in[3];
    const float* pr    = (const float*)d_in[4];
    const float* Wl1   = (const float*)d_in[5];
    const float* bl1   = (const float*)d_in[6];
    const float* Wr1   = (const float*)d_in[7];
    const float* br1   = (const float*)d_in[8];
    const float* att1  = (const float*)d_in[9];
    const float* bias1 = (const float*)d_in[10];
    const float* bn1g  = (const float*)d_in[11];
    const float* bn1b  = (const float*)d_in[12];
    const float* bn1m  = (const float*)d_in[13];
    const float* bn1v  = (const float*)d_in[14];
    const float* Wl2   = (const float*)d_in[15];
    const float* bl2   = (const float*)d_in[16];
    const float* Wr2   = (const float*)d_in[17];
    const float* br2   = (const float*)d_in[18];
    const float* att2  = (const float*)d_in[19];
    const float* bias2 = (const float*)d_in[20];
    const float* bn2g  = (const float*)d_in[21];
    const float* bn2b  = (const float*)d_in[22];
    const float* bn2m  = (const float*)d_in[23];
    const float* bn2v  = (const float*)d_in[24];
    const float* Wp    = (const float*)d_in[25];
    const float* bp    = (const float*)d_in[26];
    float* out = (float*)d_out;

    float *xl1, *xr1, *h1, *xl2, *xr2, *z;
    float *bns1, *bnt1, *bns2, *bnt2;
    int *deg, *off, *cursor, *csr_src;
    __nv_bfloat16 *As1, *As2, *Wl1s, *Wr1s, *Wl2s, *Wr2s;
    cudaGetSymbolAddress((void**)&xl1, g_xl1);
    cudaGetSymbolAddress((void**)&xr1, g_xr1);
    cudaGetSymbolAddress((void**)&h1,  g_h1);
    cudaGetSymbolAddress((void**)&xl2, g_xl2);
    cudaGetSymbolAddress((void**)&xr2, g_xr2);
    cudaGetSymbolAddress((void**)&z,   g_z);
    cudaGetSymbolAddress((void**)&bns1, g_bns1);
    cudaGetSymbolAddress((void**)&bnt1, g_bnt1);
    cudaGetSymbolAddress((void**)&bns2, g_bns2);
    cudaGetSymbolAddress((void**)&bnt2, g_bnt2);
    cudaGetSymbolAddress((void**)&deg, g_deg);
    cudaGetSymbolAddress((void**)&off, g_off);
    cudaGetSymbolAddress((void**)&cursor, g_cursor);
    cudaGetSymbolAddress((void**)&csr_src, g_csr_src);
    cudaGetSymbolAddress((void**)&As1, g_As1);
    cudaGetSymbolAddress((void**)&As2, g_As2);
    cudaGetSymbolAddress((void**)&Wl1s, g_Wl1s);
    cudaGetSymbolAddress((void**)&Wr1s, g_Wr1s);
    cudaGetSymbolAddress((void**)&Wl2s, g_Wl2s);
    cudaGetSymbolAddress((void**)&Wr2s, g_Wr2s);

    static int smem_cfg = 0;
    if (!smem_cfg) {
        cudaFuncSetAttribute(gemm_mma, cudaFuncAttributeMaxDynamicSharedMemorySize,
                             2 * STAGE_BYTES);
        smem_cfg = 1;
    }

    const int TB = 256;
    int mblk = (N_NODES + 127) / 128;              // 391
    int nwarp_blk = (N_NODES * 32 + TB - 1) / TB;

    // ---- CSR build ----
    deg_zero<<<(N_NODES + TB - 1) / TB, TB>>>(deg);
    deg_hist<<<(ETOT + TB - 1) / TB, TB>>>(ei, deg);
    scan_kernel<<<1, 1024>>>(deg, off, cursor);
    csr_scatter<<<(ETOT + TB - 1) / TB, TB>>>(ei, cursor, csr_src);

    // ---- BN folding ----
    bn_prep<<<(W1 + 255) / 256, 256>>>(bias1, bn1g, bn1b, bn1m, bn1v, bns1, bnt1, W1);
    bn_prep<<<(W2 + 255) / 256, 256>>>(bias2, bn2g, bn2b, bn2m, bn2v, bns2, bnt2, W2);

    // ---- layer 1 ----
    split_A<<<(N_NODES * K1 + TB - 1) / TB, TB>>>(x, As1, N_NODES, K1);
    split_W<<<(K1 * W1 + TB - 1) / TB, TB>>>(Wl1, Wl1s, K1, W1);
    split_W<<<(K1 * W1 + TB - 1) / TB, TB>>>(Wr1, Wr1s, K1, W1);
    {
        dim3 g1(W1 / 128, mblk);
        gemm_mma<<<g1, 256, 2 * STAGE_BYTES>>>(As1, Wl1s, bl1, xl1, N_NODES, K1S, W1);
        gemm_mma<<<g1, 256, 2 * STAGE_BYTES>>>(As1, Wr1s, br1, xr1, N_NODES, K1S, W1);
    }
    fused_agg<H1><<<nwarp_blk, TB>>>(xl1, xr1, att1, off, csr_src, bns1, bnt1, h1);

    // ---- layer 2 ----
    split_A<<<(N_NODES * K2 + TB - 1) / TB, TB>>>(h1, As2, N_NODES, K2);
    split_W<<<(K2 * W2 + TB - 1) / TB, TB>>>(Wl2, Wl2s, K2, W2);
    split_W<<<(K2 * W2 + TB - 1) / TB, TB>>>(Wr2, Wr2s, K2, W2);
    {
        dim3 g2(W2 / 128, mblk);
        gemm_mma<<<g2, 256, 2 * STAGE_BYTES>>>(As2, Wl2s, bl2, xl2, N_NODES, K2S, W2);
        gemm_mma<<<g2, 256, 2 * STAGE_BYTES>>>(As2, Wr2s, br2, xr2, N_NODES, K2S, W2);
    }
    fused_agg<H2><<<nwarp_blk, TB>>>(xl2, xr2, att2, off, csr_src, bns2, bnt2, z);

    // ---- head ----
    head_kernel<<<(N_PRED * 32 + TB - 1) / TB, TB>>>(z, pe, pr, pert, Wp, bp, out);
}

// round 6
// speedup vs baseline: 2.7959x; 1.1135x over previous
#include <cuda_runtime.h>
#include <cuda_bf16.h>
#include <math.h>
#include <cstdint>

// ---------------- problem constants ----------------
#define N_NODES 50000
#define N_EDGES 600000
#define N_PRED  200000
#define ETOT    (N_EDGES + N_NODES)
#define W1      512
#define W2      256
#define H1      4
#define H2      2
#define K1      128
#define K2      512
#define BN_EPS  1e-5f

// ---------------- scratch (device globals) ----------------
__device__ float g_c1[(size_t)N_NODES * (2 * W1)];   // [xl1 | xr1]
__device__ float g_c2[(size_t)N_NODES * (2 * W2)];   // [xl2 | xr2]
__device__ float g_z [(size_t)N_NODES * W2];

__device__ __nv_bfloat16 g_As1[(size_t)N_NODES * (2 * K1)];   // [a0|a1]
__device__ __nv_bfloat16 g_As2[(size_t)N_NODES * (2 * K2)];   // [a0|a1] (from fused_agg1)
__device__ __nv_bfloat16 g_Wc1s[(2 * W1) * (3 * K1)];         // [b0|b0|b1] rows = [Wl|Wr]
__device__ __nv_bfloat16 g_Wc2s[(2 * W2) * (3 * K2)];

__device__ float g_bc1[2 * W1];
__device__ float g_bc2[2 * W2];

__device__ int g_deg[N_NODES];
__device__ int g_off[N_NODES + 1];
__device__ int g_cursor[N_NODES];
__device__ int g_csr_src[ETOT];

__device__ float g_bns1[W1];
__device__ float g_bnt1[W1];
__device__ float g_bns2[W2];
__device__ float g_bnt2[W2];

// ---------------- helpers ----------------
__device__ __forceinline__ uint32_t smem_to_u32(const void* p) {
    uint32_t a;
    asm("{ .reg .u64 t; cvta.to.shared.u64 t, %1; cvt.u32.u64 %0, t; }" : "=r"(a) : "l"(p));
    return a;
}
#define SWZ128(b) ((b) ^ (((b) >> 3) & 0x70))

__device__ __forceinline__ void ldmatrix_x4(uint32_t* r, uint32_t addr) {
    asm volatile("ldmatrix.sync.aligned.m8n8.x4.shared.b16 {%0,%1,%2,%3}, [%4];"
                 : "=r"(r[0]), "=r"(r[1]), "=r"(r[2]), "=r"(r[3]) : "r"(addr));
}
__device__ __forceinline__ void mma16816(float* c, const uint32_t* a,
                                         uint32_t b0, uint32_t b1) {
    asm volatile("mma.sync.aligned.m16n8k16.row.col.f32.bf16.bf16.f32 "
                 "{%0,%1,%2,%3}, {%4,%5,%6,%7}, {%8,%9}, {%0,%1,%2,%3};"
                 : "+f"(c[0]), "+f"(c[1]), "+f"(c[2]), "+f"(c[3])
                 : "r"(a[0]), "r"(a[1]), "r"(a[2]), "r"(a[3]), "r"(b0), "r"(b1));
}

// ---------------- prep kernels ----------------
// A' [M, 2K] = [a0 | a1]
__global__ void split_A(const float* __restrict__ X, __nv_bfloat16* __restrict__ out,
                        int M, int K) {
    int idx = blockIdx.x * blockDim.x + threadIdx.x;
    if (idx >= M * K) return;
    int m = idx / K, k = idx - m * K;
    float a = X[idx];
    __nv_bfloat16 a0 = __float2bfloat16(a);
    __nv_bfloat16 a1 = __float2bfloat16(a - __bfloat162float(a0));
    size_t base = (size_t)m * (2 * K);
    out[base + k] = a0;
    out[base + K + k] = a1;
}

// B'' rows [Wl | Wr]: out[(n + half*Nn), 3K] = [b0 | b0 | b1], from W[K, Nn]
__global__ void split_W_pair(const float* __restrict__ Wl, const float* __restrict__ Wr,
                             __nv_bfloat16* __restrict__ out, int K, int Nn) {
    int idx = blockIdx.x * blockDim.x + threadIdx.x;
    if (idx >= 2 * K * Nn) return;
    const float* W = (idx < K * Nn) ? Wl : Wr;
    int rem = (idx < K * Nn) ? idx : idx - K * Nn;
    int noff = (idx < K * Nn) ? 0 : Nn;
    int k = rem / Nn, n = rem - k * Nn;
    float b = W[rem];
    __nv_bfloat16 b0 = __float2bfloat16(b);
    __nv_bfloat16 b1 = __float2bfloat16(b - __bfloat162float(b0));
    size_t base = (size_t)(n + noff) * (3 * K);
    out[base + k] = b0;
    out[base + K + k] = b0;
    out[base + 2 * K + k] = b1;
}

__global__ void cat2(const float* __restrict__ a, const float* __restrict__ b,
                     float* __restrict__ o, int n) {
    int i = blockIdx.x * blockDim.x + threadIdx.x;
    if (i < n) { o[i] = a[i]; o[n + i] = b[i]; }
}

// ---------------- HMMA bf16 GEMM ----------------
// C[M,Nn] = A'[M,KsA=2K] (chunk-remapped to 3K) @ B''[Nn,KsB=3K]^T + bias
// tile 128x128, K-chunk 64 bf16, 8 warps (4x2), 3-stage cp.async.
#define STAGE_BYTES 32768   // 16KB A + 16KB B per stage

__global__ __launch_bounds__(256)
void gemm_mma(const __nv_bfloat16* __restrict__ A, const __nv_bfloat16* __restrict__ B,
              const float* __restrict__ bias, float* __restrict__ C,
              int M, int KsA, int KsB, int Nn) {
    extern __shared__ __align__(1024) char sm[];
    int tid = threadIdx.x;
    int wid = tid >> 5, lane = tid & 31;
    int m0 = blockIdx.y * 128, n0 = blockIdx.x * 128;
    int wm = wid >> 1, wn = wid & 1;
    uint32_t smb = smem_to_u32(sm);

    float acc[2][8][4];
#pragma unroll
    for (int t = 0; t < 2; t++)
#pragma unroll
        for (int j = 0; j < 8; j++)
#pragma unroll
            for (int q = 0; q < 4; q++) acc[t][j][4 * 0 + q] = 0.f;

    int nch = KsB / 64;
    int nchA = KsA / 64;

    auto issue_load = [&](int c, int s) {
        uint32_t base = smb + s * STAGE_BYTES;
        int ca = (c < nchA) ? c : c - nchA;   // reuse a0 chunks for the b1 section
#pragma unroll
        for (int r = 0; r < 4; r++) {
            int idx = tid + r * 256;
            int row = idx >> 3, j = idx & 7;
            const __nv_bfloat16* gp = A + (size_t)(m0 + row) * KsA + ca * 64 + j * 8;
            uint32_t sa = base + SWZ128(row * 128 + j * 16);
            int sz = (m0 + row < M) ? 16 : 0;
            asm volatile("cp.async.cg.shared.global [%0], [%1], 16, %2;"
                         :: "r"(sa), "l"(gp), "r"(sz));
        }
#pragma unroll
        for (int r = 0; r < 4; r++) {
            int idx = tid + r * 256;
            int row = idx >> 3, j = idx & 7;
            const __nv_bfloat16* gp = B + (size_t)(n0 + row) * KsB + c * 64 + j * 8;
            uint32_t sa = base + 16384 + SWZ128(row * 128 + j * 16);
            asm volatile("cp.async.cg.shared.global [%0], [%1], 16;"
                         :: "r"(sa), "l"(gp));
        }
        asm volatile("cp.async.commit_group;");
    };

    issue_load(0, 0);
    if (nch > 1) issue_load(1, 1);

    for (int c = 0; c < nch; c++) {
        if (c + 1 < nch) asm volatile("cp.async.wait_group 1;");
        else             asm volatile("cp.async.wait_group 0;");
        __syncthreads();
        if (c + 2 < nch) issue_load(c + 2, (c + 2) % 3);

        uint32_t ab = smb + (c % 3) * STAGE_BYTES;
        uint32_t bb = ab + 16384;
#pragma unroll
        for (int kk = 0; kk < 4; kk++) {
            uint32_t af[2][4];
#pragma unroll
            for (int t = 0; t < 2; t++) {
                int rl = 32 * wm + 16 * t + (lane & 15);
                uint32_t ad = ab + SWZ128(rl * 128 + kk * 32 + (lane >> 4) * 16);
                ldmatrix_x4(af[t], ad);
            }
            uint32_t bf[4][4];
#pragma unroll
            for (int p = 0; p < 4; p++) {
                int nl = 64 * wn + 16 * p + ((lane >> 4) << 3) + (lane & 7);
                uint32_t bd = bb + SWZ128(nl * 128 + kk * 32 + ((lane >> 3) & 1) * 16);
                ldmatrix_x4(bf[p], bd);
            }
#pragma unroll
            for (int t = 0; t < 2; t++)
#pragma unroll
                for (int j = 0; j < 8; j++)
                    mma16816(acc[t][j], af[t],
                             bf[j >> 1][(j & 1) * 2], bf[j >> 1][(j & 1) * 2 + 1]);
        }
    }

#pragma unroll
    for (int t = 0; t < 2; t++) {
        int gr = m0 + 32 * wm + 16 * t + (lane >> 2);
#pragma unroll
        for (int j = 0; j < 8; j++) {
            int gc = n0 + 64 * wn + 8 * j + (lane & 3) * 2;
            float2 bi = *(const float2*)(bias + gc);
            if (gr < M) {
                float2 o = make_float2(acc[t][j][0] + bi.x, acc[t][j][1] + bi.y);
                *(float2*)(C + (size_t)gr * Nn + gc) = o;
            }
            if (gr + 8 < M) {
                float2 o = make_float2(acc[t][j][2] + bi.x, acc[t][j][3] + bi.y);
                *(float2*)(C + (size_t)(gr + 8) * Nn + gc) = o;
            }
        }
    }
}

// ---------------- BN prep ----------------
__global__ void bn_prep(const float* __restrict__ bias, const float* __restrict__ g,
                        const float* __restrict__ b, const float* __restrict__ m,
                        const float* __restrict__ v, float* __restrict__ s,
                        float* __restrict__ t, int n) {
    int i = blockIdx.x * blockDim.x + threadIdx.x;
    if (i < n) {
        float sc = g[i] * rsqrtf(v[i] + BN_EPS);
        s[i] = sc;
        t[i] = b[i] + (bias[i] - m[i]) * sc;
    }
}

// ---------------- CSR build ----------------
__global__ void deg_zero(int* deg) {
    int i = blockIdx.x * blockDim.x + threadIdx.x;
    if (i < N_NODES) deg[i] = 0;
}
__global__ void deg_hist(const int* __restrict__ ei, int* __restrict__ deg) {
    int i = blockIdx.x * blockDim.x + threadIdx.x;
    if (i >= ETOT) return;
    int dst = (i < N_EDGES) ? ei[N_EDGES + i] : (i - N_EDGES);
    atomicAdd(&deg[dst], 1);
}
__global__ void scan_kernel(const int* __restrict__ deg, int* __restrict__ off,
                            int* __restrict__ cursor) {
    __shared__ int warp_sums[32];
    const int T = 1024;
    int tid = threadIdx.x;
    int chunk = (N_NODES + T - 1) / T;
    int start = tid * chunk;
    int end = min(start + chunk, N_NODES);
    int local = 0;
    for (int i = start; i < end; i++) local += deg[i];
    int lane = tid & 31, wid = tid >> 5;
    int v = local;
#pragma unroll
    for (int o = 1; o < 32; o <<= 1) {
        int u = __shfl_up_sync(0xFFFFFFFFu, v, o);
        if (lane >= o) v += u;
    }
    if (lane == 31) warp_sums[wid] = v;
    __syncthreads();
    if (wid == 0) {
        int s = warp_sums[lane];
#pragma unroll
        for (int o = 1; o < 32; o <<= 1) {
            int u = __shfl_up_sync(0xFFFFFFFFu, s, o);
            if (lane >= o) s += u;
        }
        warp_sums[lane] = s;
    }
    __syncthreads();
    int excl = v - local + (wid > 0 ? warp_sums[wid - 1] : 0);
    int run = excl;
    for (int i = start; i < end; i++) {
        off[i] = run;
        cursor[i] = run;
        run += deg[i];
    }
    if (tid == T - 1) off[N_NODES] = run;
}
__global__ void csr_scatter(const int* __restrict__ ei, int* __restrict__ cursor,
                            int* __restrict__ csr_src) {
    int i = blockIdx.x * blockDim.x + threadIdx.x;
    if (i >= ETOT) return;
    int src, dst;
    if (i < N_EDGES) { src = ei[i]; dst = ei[N_EDGES + i]; }
    else             { src = dst = i - N_EDGES; }
    int pos = atomicAdd(&cursor[dst], 1);
    csr_src[pos] = src;
}

// ---------------- fused GATv2 aggregation (one warp per dst node) --------------
// xl/xr are column slices of the concatenated GEMM output (row stride ldx).
// OUTBF16: write [a0|a1] bf16 split (feeds next GEMM); else fp32.
template<int H, bool OUTBF16>
__global__ __launch_bounds__(256)
void fused_agg(const float* __restrict__ xl, const float* __restrict__ xr, int ldx,
               const float* __restrict__ att,
               const int* __restrict__ off, const int* __restrict__ csr_src,
               const float* __restrict__ bns, const float* __restrict__ bnt,
               void* __restrict__ outp) {
    int node = (blockIdx.x * blockDim.x + threadIdx.x) >> 5;
    int lane = threadIdx.x & 31;
    if (node >= N_NODES) return;
    const int Wd = H * 128;

    const float4* xr4 = (const float4*)(xr + (size_t)node * ldx);
    const float4* at4 = (const float4*)att;

    float4 xrr[H], attr[H], acc[H];
    float m[H], sum[H];
#pragma unroll
    for (int h = 0; h < H; h++) {
        xrr[h]  = xr4[h * 32 + lane];
        attr[h] = at4[h * 32 + lane];
        acc[h]  = make_float4(0.f, 0.f, 0.f, 0.f);
        m[h]    = -INFINITY;
        sum[h]  = 0.f;
    }

    int e0 = off[node], e1 = off[node + 1];
    int src = csr_src[e0];
    float4 v[H];
    {
        const float4* xs = (const float4*)(xl + (size_t)src * ldx);
#pragma unroll
        for (int h = 0; h < H; h++) v[h] = xs[h * 32 + lane];
    }

    for (int e = e0; e < e1; e++) {
        int nsrc = (e + 1 < e1) ? csr_src[e + 1] : src;
        const float4* xn = (const float4*)(xl + (size_t)nsrc * ldx);
        float4 vn[H];
#pragma unroll
        for (int h = 0; h < H; h++) vn[h] = xn[h * 32 + lane];

#pragma unroll
        for (int h = 0; h < H; h++) {
            float ex = v[h].x + xrr[h].x; ex = ex > 0.f ? ex : 0.2f * ex;
            float ey = v[h].y + xrr[h].y; ey = ey > 0.f ? ey : 0.2f * ey;
            float ez = v[h].z + xrr[h].z; ez = ez > 0.f ? ez : 0.2f * ez;
            float ew = v[h].w + xrr[h].w; ew = ew > 0.f ? ew : 0.2f * ew;
            float s = ex * attr[h].x + ey * attr[h].y + ez * attr[h].z + ew * attr[h].w;
#pragma unroll
            for (int o = 16; o > 0; o >>= 1) s += __shfl_xor_sync(0xFFFFFFFFu, s, o);

            float mn = fmaxf(m[h], s);
            float c  = __expf(m[h] - mn);
            float p  = __expf(s - mn);
            sum[h]   = sum[h] * c + p;
            acc[h].x = acc[h].x * c + p * v[h].x;
            acc[h].y = acc[h].y * c + p * v[h].y;
            acc[h].z = acc[h].z * c + p * v[h].z;
            acc[h].w = acc[h].w * c + p * v[h].w;
            m[h] = mn;
        }
#pragma unroll
        for (int h = 0; h < H; h++) v[h] = vn[h];
    }

#pragma unroll
    for (int h = 0; h < H; h++) {
        int cbase = h * 128 + lane * 4;
        float4 sc = *(const float4*)(bns + cbase);
        float4 tt = *(const float4*)(bnt + cbase);
        float inv = 1.f / sum[h];
        float4 o;
        o.x = fmaxf(fmaf(acc[h].x * inv, sc.x, tt.x), 0.f);
        o.y = fmaxf(fmaf(acc[h].y * inv, sc.y, tt.y), 0.f);
        o.z = fmaxf(fmaf(acc[h].z * inv, sc.z, tt.z), 0.f);
        o.w = fmaxf(fmaf(acc[h].w * inv, sc.w, tt.w), 0.f);
        if (OUTBF16) {
            __nv_bfloat16* out = (__nv_bfloat16*)outp;
            size_t base = (size_t)node * (2 * Wd);
            __nv_bfloat16 h0x = __float2bfloat16(o.x), h0y = __float2bfloat16(o.y);
            __nv_bfloat16 h0z = __float2bfloat16(o.z), h0w = __float2bfloat16(o.w);
            __nv_bfloat16 h1x = __float2bfloat16(o.x - __bfloat162float(h0x));
            __nv_bfloat16 h1y = __float2bfloat16(o.y - __bfloat162float(h0y));
            __nv_bfloat16 h1z = __float2bfloat16(o.z - __bfloat162float(h0z));
            __nv_bfloat16 h1w = __float2bfloat16(o.w - __bfloat162float(h0w));
            uint2 p0, p1;
            p0.x = ((uint32_t)__bfloat16_as_ushort(h0y) << 16) | __bfloat16_as_ushort(h0x);
            p0.y = ((uint32_t)__bfloat16_as_ushort(h0w) << 16) | __bfloat16_as_ushort(h0z);
            p1.x = ((uint32_t)__bfloat16_as_ushort(h1y) << 16) | __bfloat16_as_ushort(h1x);
            p1.y = ((uint32_t)__bfloat16_as_ushort(h1w) << 16) | __bfloat16_as_ushort(h1z);
            *(uint2*)(out + base + cbase) = p0;
            *(uint2*)(out + base + Wd + cbase) = p1;
        } else {
            float* out = (float*)outp;
            *(float4*)(out + (size_t)node * Wd + cbase) = o;
        }
    }
}

// ---------------- prediction head ----------------
__global__ void head_kernel(const float* __restrict__ z, const int* __restrict__ pe,
                            const float* __restrict__ pr, const float* __restrict__ pert,
                            const float* __restrict__ Wp, const float* __restrict__ bp,
                            float* __restrict__ out) {
    __shared__ float sw[(W2 * 2 + 3) * 2];
    for (int i = threadIdx.x; i < (W2 * 2 + 3) * 2; i += blockDim.x) sw[i] = Wp[i];
    __syncthreads();

    int w = (blockIdx.x * blockDim.x + threadIdx.x) >> 5;
    int lane = threadIdx.x & 31;
    if (w >= N_PRED) return;
    int s = pe[w], d = pe[N_PRED + w];
    const float4* zs = (const float4*)(z + (size_t)s * W2);
    const float4* zd = (const float4*)(z + (size_t)d * W2);

    float a0 = 0.f, a1 = 0.f;
#pragma unroll
    for (int q = 0; q < 2; q++) {
        int r = lane * 2 + q;
        float4 vz = zs[r];
        int base = (r * 4) * 2;
        a0 += vz.x * sw[base] + vz.y * sw[base + 2] + vz.z * sw[base + 4] + vz.w * sw[base + 6];
        a1 += vz.x * sw[base + 1] + vz.y * sw[base + 3] + vz.z * sw[base + 5] + vz.w * sw[base + 7];
        float4 vd = zd[r];
        int base2 = (W2 + r * 4) * 2;
        a0 += vd.x * sw[base2] + vd.y * sw[base2 + 2] + vd.z * sw[base2 + 4] + vd.w * sw[base2 + 6];
        a1 += vd.x * sw[base2 + 1] + vd.y * sw[base2 + 3] + vd.z * sw[base2 + 5] + vd.w * sw[base2 + 7];
    }
    if (lane == 0) {
        float prs = pr[s], prd = pr[d], pp = pert[s] * pert[d];
        int b0 = (2 * W2) * 2;
        a0 += prs * sw[b0] + prd * sw[b0 + 2] + pp * sw[b0 + 4];
        a1 += prs * sw[b0 + 1] + prd * sw[b0 + 3] + pp * sw[b0 + 5];
    }
#pragma unroll
    for (int o = 16; o > 0; o >>= 1) {
        a0 += __shfl_xor_sync(0xFFFFFFFFu, a0, o);
        a1 += __shfl_xor_sync(0xFFFFFFFFu, a1, o);
    }
    if (lane == 0) {
        out[(size_t)w * 2 + 0] = a0 + bp[0];
        out[(size_t)w * 2 + 1] = a1 + bp[1];
    }
}

// ---------------- launch ----------------
extern "C" void kernel_launch(void* const* d_in, const int* in_sizes, int n_in,
                              void* d_out, int out_size) {
    const float* x     = (const float*)d_in[0];
    const int*   ei    = (const int*)d_in[1];
    const int*   pe    = (const int*)d_in[2];
    const float* pert  = (const float*)d_in[3];
    const float* pr    = (const float*)d_in[4];
    const float* Wl1   = (const float*)d_in[5];
    const float* bl1   = (const float*)d_in[6];
    const float* Wr1   = (const float*)d_in[7];
    const float* br1   = (const float*)d_in[8];
    const float* att1  = (const float*)d_in[9];
    const float* bias1 = (const float*)d_in[10];
    const float* bn1g  = (const float*)d_in[11];
    const float* bn1b  = (const float*)d_in[12];
    const float* bn1m  = (const float*)d_in[13];
    const float* bn1v  = (const float*)d_in[14];
    const float* Wl2   = (const float*)d_in[15];
    const float* bl2   = (const float*)d_in[16];
    const float* Wr2   = (const float*)d_in[17];
    const float* br2   = (const float*)d_in[18];
    const float* att2  = (const float*)d_in[19];
    const float* bias2 = (const float*)d_in[20];
    const float* bn2g  = (const float*)d_in[21];
    const float* bn2b  = (const float*)d_in[22];
    const float* bn2m  = (const float*)d_in[23];
    const float* bn2v  = (const float*)d_in[24];
    const float* Wp    = (const float*)d_in[25];
    const float* bp    = (const float*)d_in[26];
    float* out = (float*)d_out;

    float *c1, *c2, *z, *bc1, *bc2;
    float *bns1, *bnt1, *bns2, *bnt2;
    int *deg, *off, *cursor, *csr_src;
    __nv_bfloat16 *As1, *As2, *Wc1s, *Wc2s;
    cudaGetSymbolAddress((void**)&c1, g_c1);
    cudaGetSymbolAddress((void**)&c2, g_c2);
    cudaGetSymbolAddress((void**)&z,  g_z);
    cudaGetSymbolAddress((void**)&bc1, g_bc1);
    cudaGetSymbolAddress((void**)&bc2, g_bc2);
    cudaGetSymbolAddress((void**)&bns1, g_bns1);
    cudaGetSymbolAddress((void**)&bnt1, g_bnt1);
    cudaGetSymbolAddress((void**)&bns2, g_bns2);
    cudaGetSymbolAddress((void**)&bnt2, g_bnt2);
    cudaGetSymbolAddress((void**)&deg, g_deg);
    cudaGetSymbolAddress((void**)&off, g_off);
    cudaGetSymbolAddress((void**)&cursor, g_cursor);
    cudaGetSymbolAddress((void**)&csr_src, g_csr_src);
    cudaGetSymbolAddress((void**)&As1, g_As1);
    cudaGetSymbolAddress((void**)&As2, g_As2);
    cudaGetSymbolAddress((void**)&Wc1s, g_Wc1s);
    cudaGetSymbolAddress((void**)&Wc2s, g_Wc2s);

    static int smem_cfg = 0;
    if (!smem_cfg) {
        cudaFuncSetAttribute(gemm_mma, cudaFuncAttributeMaxDynamicSharedMemorySize,
                             3 * STAGE_BYTES);
        smem_cfg = 1;
    }

    const int TB = 256;
    int mblk = (N_NODES + 127) / 128;              // 391
    int nwarp_blk = (N_NODES * 32 + TB - 1) / TB;

    // ---- layer-1 prep + GEMM (gemm is launch #4 for profiling) ----
    cat2<<<(W1 + 255) / 256, 256>>>(bl1, br1, bc1, W1);
    split_A<<<(N_NODES * K1 + TB - 1) / TB, TB>>>(x, As1, N_NODES, K1);
    split_W_pair<<<(2 * K1 * W1 + TB - 1) / TB, TB>>>(Wl1, Wr1, Wc1s, K1, W1);
    {
        dim3 g1((2 * W1) / 128, mblk);
        gemm_mma<<<g1, 256, 3 * STAGE_BYTES>>>(As1, Wc1s, bc1, c1,
                                               N_NODES, 2 * K1, 3 * K1, 2 * W1);
    }

    // ---- CSR build + BN folding + layer-2 prep (overlap with nothing; cheap) ----
    deg_zero<<<(N_NODES + TB - 1) / TB, TB>>>(deg);
    deg_hist<<<(ETOT + TB - 1) / TB, TB>>>(ei, deg);
    scan_kernel<<<1, 1024>>>(deg, off, cursor);
    csr_scatter<<<(ETOT + TB - 1) / TB, TB>>>(ei, cursor, csr_src);
    bn_prep<<<(W1 + 255) / 256, 256>>>(bias1, bn1g, bn1b, bn1m, bn1v, bns1, bnt1, W1);
    bn_prep<<<(W2 + 255) / 256, 256>>>(bias2, bn2g, bn2b, bn2m, bn2v, bns2, bnt2, W2);
    cat2<<<(W2 + 255) / 256, 256>>>(bl2, br2, bc2, W2);
    split_W_pair<<<(2 * K2 * W2 + TB - 1) / TB, TB>>>(Wl2, Wr2, Wc2s, K2, W2);

    // ---- layer-1 aggregation -> bf16 [a0|a1] for layer-2 GEMM ----
    fused_agg<H1, true><<<nwarp_blk, TB>>>(c1, c1 + W1, 2 * W1, att1,
                                           off, csr_src, bns1, bnt1, As2);

    // ---- layer 2 ----
    {
        dim3 g2((2 * W2) / 128, mblk);
        gemm_mma<<<g2, 256, 3 * STAGE_BYTES>>>(As2, Wc2s, bc2, c2,
                                               N_NODES, 2 * K2, 3 * K2, 2 * W2);
    }
    fused_agg<H2, false><<<nwarp_blk, TB>>>(c2, c2 + W2, 2 * W2, att2,
                                            off, csr_src, bns2, bnt2, z);

    // ---- head ----
    head_kernel<<<(N_PRED * 32 + TB - 1) / TB, TB>>>(z, pe, pr, pert, Wp, bp, out);
}